// round 3
// baseline (speedup 1.0000x reference)
#include <cuda_runtime.h>

#define BB 2
#define NRAW 16384
#define NKP 2048
#define MVOX 8192
#define HBEV 200
#define WBEV 176
#define CBEV 256
#define FDIM 416
#define BN_SCALE_F 0.9999950000374997f

typedef unsigned short ushort_t;

// ---------------- scratch (static device globals; no allocation) ----------------
__device__ float4   g_kp[BB * NKP];          // keypoint xyz
__device__ float4   g_rawp[BB * NRAW];       // raw points: x,y,z,intensity
__device__ float4   g_convp[BB * MVOX];      // voxel centers
__device__ ushort_t g_ridx0[BB * NKP * 16];
__device__ ushort_t g_ridx1[BB * NKP * 16];
__device__ ushort_t g_cidx0[BB * NKP * 16];
__device__ ushort_t g_cidx1[BB * NKP * 32];
__device__ int      g_rcnt0[BB * NKP], g_rcnt1[BB * NKP];
__device__ int      g_ccnt0[BB * NKP], g_ccnt1[BB * NKP];
__device__ float    g_feats[BB * NKP * FDIM];

// ---------------- PTX helpers (cluster DSMEM + mbarrier) ----------------
__device__ __forceinline__ unsigned smem_u32(const void* p) {
    return (unsigned)__cvta_generic_to_shared(const_cast<void*>(p));
}
__device__ __forceinline__ unsigned cluster_rank() {
    unsigned r; asm("mov.u32 %0, %%cluster_ctarank;" : "=r"(r)); return r;
}
__device__ __forceinline__ unsigned mapa_u32(unsigned local, unsigned rank) {
    unsigned r;
    asm("mapa.shared::cluster.u32 %0, %1, %2;" : "=r"(r) : "r"(local), "r"(rank));
    return r;
}
__device__ __forceinline__ void st_cluster_f32(unsigned addr, float v) {
    asm volatile("st.shared::cluster.f32 [%0], %1;" :: "r"(addr), "f"(v) : "memory");
}
__device__ __forceinline__ void st_cluster_u32(unsigned addr, unsigned v) {
    asm volatile("st.shared::cluster.u32 [%0], %1;" :: "r"(addr), "r"(v) : "memory");
}
__device__ __forceinline__ void bar_init(unsigned addr, unsigned cnt) {
    asm volatile("mbarrier.init.shared.b64 [%0], %1;" :: "r"(addr), "r"(cnt) : "memory");
}
__device__ __forceinline__ void bar_arrive_cluster(unsigned addr) {
    asm volatile("mbarrier.arrive.release.cluster.shared::cluster.b64 _, [%0];"
                 :: "r"(addr) : "memory");
}
__device__ __forceinline__ void bar_wait_parity(unsigned addr, unsigned parity) {
    unsigned done;
    do {
        asm volatile("{\n\t.reg .pred p;\n\t"
                     "mbarrier.try_wait.parity.acquire.cluster.shared::cta.b64 p, [%1], %2;\n\t"
                     "selp.b32 %0, 1, 0, p;\n\t}"
                     : "=r"(done) : "r"(addr), "r"(parity) : "memory");
    } while (!done);
}
__device__ __forceinline__ void cluster_sync_all() {
    asm volatile("barrier.cluster.arrive.aligned;" ::: "memory");
    asm volatile("barrier.cluster.wait.aligned;" ::: "memory");
}

// ---------------- pack kernels ----------------
__global__ void pack_raw_kernel(const float* __restrict__ points) {
    int i = blockIdx.x * blockDim.x + threadIdx.x;
    if (i >= BB * NRAW) return;
    const float* r = points + (size_t)i * 5;
    g_rawp[i] = make_float4(r[1], r[2], r[3], r[4]);
}

__global__ void pack_conv_kernel(const int* __restrict__ vc) {
    int i = blockIdx.x * blockDim.x + threadIdx.x;
    if (i >= BB * MVOX) return;
    const int* r = vc + (size_t)i * 4;
    float cx = __fadd_rn(__fmul_rn(__fadd_rn((float)r[3], 0.5f), 0.2f), 0.0f);
    float cy = __fadd_rn(__fmul_rn(__fadd_rn((float)r[2], 0.5f), 0.2f), -40.0f);
    float cz = __fadd_rn(__fmul_rn(__fadd_rn((float)r[1], 0.5f), 0.4f), -3.0f);
    g_convp[i] = make_float4(cx, cy, cz, 0.0f);
}

// ---------------- FPS: 8-CTA cluster per batch, registers + mbarrier ping-pong ----------------
#define FPS_G 8
#define FPS_THREADS 256
#define PTS_PER_CTA (NRAW / FPS_G)            // 2048
#define PTS_PER_THR (PTS_PER_CTA / FPS_THREADS) // 8

__global__ void __cluster_dims__(FPS_G, 1, 1)
__launch_bounds__(FPS_THREADS, 1)
fps_cluster_kernel(const float* __restrict__ points) {
    __shared__ float sx[PTS_PER_CTA], sy[PTS_PER_CTA], sz[PTS_PER_CTA];
    __shared__ float red_v[8]; __shared__ int red_i[8];
    __shared__ unsigned long long gather_bar, bcast_bar;
    // gather slots (only meaningful in rank 0's SMEM)
    __shared__ float slot_v[FPS_G], slot_x[FPS_G], slot_y[FPS_G], slot_z[FPS_G];
    __shared__ unsigned slot_i[FPS_G];
    __shared__ float win_x, win_y, win_z;

    const int tid = threadIdx.x;
    const unsigned rank = cluster_rank();
    const int b = blockIdx.x / FPS_G;
    const int ctaBase = (int)rank * PTS_PER_CTA;
    const float* P = points + (size_t)b * NRAW * 5;
    const unsigned FULL = 0xffffffffu;

    if (tid == 0) {
        bar_init(smem_u32(&gather_bar), FPS_G);
        bar_init(smem_u32(&bcast_bar), 1);
    }
    __syncthreads();
    cluster_sync_all();   // mbarriers visible cluster-wide before any arrive

    // load this CTA's 2048 points: registers + SMEM copy (for leader coord lookup)
    float px[PTS_PER_THR], py[PTS_PER_THR], pz[PTS_PER_THR], dist[PTS_PER_THR];
#pragma unroll
    for (int j = 0; j < PTS_PER_THR; ++j) {
        int li = tid + j * FPS_THREADS;
        int gidx = ctaBase + li;
        float x = P[(size_t)gidx * 5 + 1];
        float y = P[(size_t)gidx * 5 + 2];
        float z = P[(size_t)gidx * 5 + 3];
        px[j] = x; py[j] = y; pz[j] = z;
        sx[li] = x; sy[li] = y; sz[li] = z;
        dist[j] = 1e10f;
    }
    __syncthreads();

    // initial winner = global point 0
    float wx = P[1], wy = P[2], wz = P[3];
    if (rank == 0 && tid == 0) g_kp[b * NKP] = make_float4(wx, wy, wz, 0.0f);

    const unsigned a_gather = (rank == 0) ? smem_u32(&gather_bar)
                                          : mapa_u32(smem_u32(&gather_bar), 0);
    const unsigned a_slot_v = mapa_u32(smem_u32(&slot_v[rank]), 0);
    const unsigned a_slot_x = mapa_u32(smem_u32(&slot_x[rank]), 0);
    const unsigned a_slot_y = mapa_u32(smem_u32(&slot_y[rank]), 0);
    const unsigned a_slot_z = mapa_u32(smem_u32(&slot_z[rank]), 0);
    const unsigned a_slot_i = mapa_u32(smem_u32(&slot_i[rank]), 0);
    const unsigned a_bcast_local = smem_u32(&bcast_bar);

    for (int it = 1; it < NKP; ++it) {
        const unsigned parity = (unsigned)((it - 1) & 1);
        // --- distance update + per-thread argmax (exact mul/add arithmetic) ---
        float bv = -1.0f; int bi = 0;
#pragma unroll
        for (int j = 0; j < PTS_PER_THR; ++j) {
            float dx = __fsub_rn(px[j], wx);
            float dy = __fsub_rn(py[j], wy);
            float dz = __fsub_rn(pz[j], wz);
            float d  = __fadd_rn(__fadd_rn(__fmul_rn(dx, dx), __fmul_rn(dy, dy)),
                                 __fmul_rn(dz, dz));
            float dm = fminf(dist[j], d);
            dist[j] = dm;
            if (dm > bv) { bv = dm; bi = ctaBase + tid + j * FPS_THREADS; }
        }
        // --- warp reduce (ties -> lowest index) ---
#pragma unroll
        for (int off = 16; off > 0; off >>= 1) {
            float ov = __shfl_down_sync(FULL, bv, off);
            int   oi = __shfl_down_sync(FULL, bi, off);
            if (ov > bv || (ov == bv && oi < bi)) { bv = ov; bi = oi; }
        }
        if ((tid & 31) == 0) { red_v[tid >> 5] = bv; red_i[tid >> 5] = bi; }
        __syncthreads();

        if (tid == 0) {
            // cross-warp reduce (8 partials, serial)
            float cv = red_v[0]; int ci = red_i[0];
#pragma unroll
            for (int w = 1; w < 8; ++w) {
                float v = red_v[w]; int i2 = red_i[w];
                if (v > cv || (v == cv && i2 < ci)) { cv = v; ci = i2; }
            }
            int li = ci - ctaBase;
            // send (v, idx, xyz) to rank 0's gather slots, then release-arrive
            st_cluster_f32(a_slot_v, cv);
            st_cluster_u32(a_slot_i, (unsigned)ci);
            st_cluster_f32(a_slot_x, sx[li]);
            st_cluster_f32(a_slot_y, sy[li]);
            st_cluster_f32(a_slot_z, sz[li]);
            bar_arrive_cluster(a_gather);

            if (rank == 0) {
                bar_wait_parity(smem_u32(&gather_bar), parity);
                float gv = slot_v[0]; unsigned gidx = slot_i[0];
                float gx = slot_x[0], gy = slot_y[0], gz = slot_z[0];
#pragma unroll
                for (int r = 1; r < FPS_G; ++r) {
                    float v = slot_v[r]; unsigned i2 = slot_i[r];
                    if (v > gv || (v == gv && i2 < gidx)) {
                        gv = v; gidx = i2;
                        gx = slot_x[r]; gy = slot_y[r]; gz = slot_z[r];
                    }
                }
                g_kp[b * NKP + it] = make_float4(gx, gy, gz, 0.0f);
                // broadcast winner coords + arrive on every CTA's bcast barrier
#pragma unroll
                for (int r = 0; r < FPS_G; ++r) {
                    st_cluster_f32(mapa_u32(smem_u32(&win_x), r), gx);
                    st_cluster_f32(mapa_u32(smem_u32(&win_y), r), gy);
                    st_cluster_f32(mapa_u32(smem_u32(&win_z), r), gz);
                    bar_arrive_cluster(mapa_u32(a_bcast_local, r));
                }
            }
        }
        // --- all threads: wait for broadcast, pick up new winner ---
        bar_wait_parity(a_bcast_local, parity);
        wx = win_x; wy = win_y; wz = win_z;
    }
}

// ---------------- bilinear BEV sampling ----------------
__global__ void bilinear_kernel(const float* __restrict__ spatial) {
    int gi = blockIdx.x;              // b*NKP + m
    int b = gi / NKP;
    float4 kp = g_kp[gi];
    float xi = __fdiv_rn(__fdiv_rn(__fsub_rn(kp.x, 0.0f), 0.05f), 8.0f);
    float yi = __fdiv_rn(__fdiv_rn(__fsub_rn(kp.y, -40.0f), 0.05f), 8.0f);
    float xf = floorf(xi), yf = floorf(yi);
    int x0 = min(max((int)xf, 0), WBEV - 1);
    int x1 = min(max((int)xf + 1, 0), WBEV - 1);
    int y0 = min(max((int)yf, 0), HBEV - 1);
    int y1 = min(max((int)yf + 1, 0), HBEV - 1);
    float x0f = (float)x0, x1f = (float)x1, y0f = (float)y0, y1f = (float)y1;
    float wa = __fmul_rn(__fsub_rn(xi, x0f), __fsub_rn(y1f, yi));
    float wb = __fmul_rn(__fsub_rn(x1f, xi), __fsub_rn(y1f, yi));
    float wc = __fmul_rn(__fsub_rn(x1f, xi), __fsub_rn(yi, y0f));
    float wd = __fmul_rn(__fsub_rn(xi, x0f), __fsub_rn(yi, y0f));

    const float* sf = spatial + (size_t)b * CBEV * HBEV * WBEV;
    int o00 = y0 * WBEV + x0, o01 = y0 * WBEV + x1;
    int o10 = y1 * WBEV + x0, o11 = y1 * WBEV + x1;
    for (int c = threadIdx.x; c < CBEV; c += blockDim.x) {
        const float* ch = sf + (size_t)c * HBEV * WBEV;
        float fd = ch[o00], fc = ch[o01], fa = ch[o10], fb = ch[o11];
        float out = __fadd_rn(__fadd_rn(__fadd_rn(__fmul_rn(fd, wb), __fmul_rn(fc, wa)),
                                        __fmul_rn(fa, wc)), __fmul_rn(fb, wd));
        g_feats[(size_t)gi * FDIM + c] = out;
    }
}

// ---------------- ball-query: warp per keypoint, ballot first-N ascending ----------------
template <bool CONV>
__global__ void scan_warp_kernel() {
    constexpr int NPTS = CONV ? MVOX : NRAW;
    constexpr int NS0 = 16;
    constexpr int NS1 = CONV ? 32 : 16;
    const float R0SQ = CONV ? (float)(1.2 * 1.2) : (float)(0.4 * 0.4);
    const float R1SQ = CONV ? (float)(2.4 * 2.4) : (float)(0.8 * 0.8);
    const unsigned FULL = 0xffffffffu;

    int warp = threadIdx.x >> 5, lane = threadIdx.x & 31;
    int m = blockIdx.x * (blockDim.x >> 5) + warp;
    int b = blockIdx.y;
    int gi = b * NKP + m;
    float4 kp = g_kp[gi];
    const float4* pts = (CONV ? g_convp : g_rawp) + (size_t)b * NPTS;
    ushort_t* o0 = (CONV ? g_cidx0 : g_ridx0) + (size_t)gi * NS0;
    ushort_t* o1 = (CONV ? g_cidx1 : g_ridx1) + (size_t)gi * NS1;

    int c0 = 0, c1 = 0;
    const unsigned below = (1u << lane) - 1u;
    for (int base = 0; base < NPTS; base += 32) {
        float4 p = __ldg(&pts[base + lane]);
        float dx = __fsub_rn(kp.x, p.x);
        float dy = __fsub_rn(kp.y, p.y);
        float dz = __fsub_rn(kp.z, p.z);
        float d2 = __fadd_rn(__fadd_rn(__fmul_rn(dx, dx), __fmul_rn(dy, dy)),
                             __fmul_rn(dz, dz));
        bool h1 = d2 < R1SQ;
        bool h0 = d2 < R0SQ;
        unsigned m1 = __ballot_sync(FULL, h1);
        if (m1) {
            unsigned m0 = __ballot_sync(FULL, h0);
            if (h1) {
                int pos = c1 + __popc(m1 & below);
                if (pos < NS1) o1[pos] = (ushort_t)(base + lane);
            }
            if (h0) {
                int pos = c0 + __popc(m0 & below);
                if (pos < NS0) o0[pos] = (ushort_t)(base + lane);
            }
            c1 += __popc(m1);
            c0 += __popc(m0);
            if (c1 >= NS1 && c0 >= NS0) break;
        } else {
            __ballot_sync(FULL, h0);  // keep ballot count symmetric (no-op)
        }
    }
    if (lane == 0) {
        if (CONV) { g_ccnt0[gi] = min(c0, NS0); g_ccnt1[gi] = min(c1, NS1); }
        else      { g_rcnt0[gi] = min(c0, NS0); g_rcnt1[gi] = min(c1, NS1); }
    }
}

// ---------------- raw SA MLP: thread per (kp, level), 4->16->16, maxpool ----------------
__global__ void raw_mlp_kernel(const float* __restrict__ w0, const float* __restrict__ gg0,
                               const float* __restrict__ bb0, const float* __restrict__ w1,
                               const float* __restrict__ gg1, const float* __restrict__ bb1) {
    int lvl = blockIdx.y, b = blockIdx.z;
    __shared__ float sW0[64], sW1[256], sS0[16], sB0[16], sS1[16], sB1[16];
    for (int i = threadIdx.x; i < 64; i += blockDim.x) sW0[i] = w0[lvl * 64 + i];
    for (int i = threadIdx.x; i < 256; i += blockDim.x) sW1[i] = w1[lvl * 256 + i];
    if (threadIdx.x < 16) {
        int c = threadIdx.x;
        sS0[c] = gg0[lvl * 16 + c] * BN_SCALE_F; sB0[c] = bb0[lvl * 16 + c];
        sS1[c] = gg1[lvl * 16 + c] * BN_SCALE_F; sB1[c] = bb1[lvl * 16 + c];
    }
    __syncthreads();

    int m = blockIdx.x * blockDim.x + threadIdx.x;
    int gi = b * NKP + m;
    int cnt = lvl ? g_rcnt1[gi] : g_rcnt0[gi];
    const ushort_t* idxarr = (lvl ? g_ridx1 : g_ridx0) + (size_t)gi * 16;
    float4 kp = g_kp[gi];

    float pooled[16];
#pragma unroll
    for (int c = 0; c < 16; ++c) pooled[c] = -1e30f;

    for (int s = 0; s < cnt; ++s) {
        int idx = idxarr[s];
        float4 p = g_rawp[(size_t)b * NRAW + idx];
        float g0v = p.x - kp.x, g1v = p.y - kp.y, g2v = p.z - kp.z, g3v = p.w;
        float h[16];
#pragma unroll
        for (int c = 0; c < 16; ++c) {
            float a = g0v * sW0[c] + g1v * sW0[16 + c] + g2v * sW0[32 + c] + g3v * sW0[48 + c];
            h[c] = fmaxf(fmaf(a, sS0[c], sB0[c]), 0.0f);
        }
#pragma unroll
        for (int c = 0; c < 16; ++c) {
            float a = 0.0f;
#pragma unroll
            for (int j = 0; j < 16; ++j) a = fmaf(h[j], sW1[j * 16 + c], a);
            float v = fmaxf(fmaf(a, sS1[c], sB1[c]), 0.0f);
            pooled[c] = fmaxf(pooled[c], v);
        }
    }
    float* dst = g_feats + (size_t)gi * FDIM + 256 + lvl * 16;
#pragma unroll
    for (int c = 0; c < 16; ++c) dst[c] = (cnt > 0) ? pooled[c] : 0.0f;
}

// ---------------- conv SA MLP: warp per (kp, level), 67->64->64, maxpool ----------------
__global__ void conv_mlp_kernel(const float* __restrict__ vfeat,
                                const float* __restrict__ w0, const float* __restrict__ gg0,
                                const float* __restrict__ bb0, const float* __restrict__ w1,
                                const float* __restrict__ gg1, const float* __restrict__ bb1) {
    int lvl = blockIdx.y, b = blockIdx.z;
    __shared__ float sW0[67 * 64], sW1[64 * 64];
    __shared__ float sS0[64], sB0[64], sS1[64], sB1[64];
    __shared__ float sG[8][68], sH[8][64];
    for (int i = threadIdx.x; i < 67 * 64; i += blockDim.x) sW0[i] = w0[lvl * 67 * 64 + i];
    for (int i = threadIdx.x; i < 64 * 64; i += blockDim.x) sW1[i] = w1[lvl * 64 * 64 + i];
    if (threadIdx.x < 64) {
        int c = threadIdx.x;
        sS0[c] = gg0[lvl * 64 + c] * BN_SCALE_F; sB0[c] = bb0[lvl * 64 + c];
        sS1[c] = gg1[lvl * 64 + c] * BN_SCALE_F; sB1[c] = bb1[lvl * 64 + c];
    }
    __syncthreads();

    int warp = threadIdx.x >> 5, lane = threadIdx.x & 31;
    int m = blockIdx.x * 8 + warp;
    int gi = b * NKP + m;
    int cnt = lvl ? g_ccnt1[gi] : g_ccnt0[gi];
    const ushort_t* idxarr = lvl ? (g_cidx1 + (size_t)gi * 32) : (g_cidx0 + (size_t)gi * 16);
    float4 kp = g_kp[gi];
    float p0 = -1e30f, p1 = -1e30f;

    for (int s = 0; s < cnt; ++s) {
        int idx = idxarr[s];
        float4 pt = g_convp[(size_t)b * MVOX + idx];
        const float* vf = vfeat + ((size_t)b * MVOX + idx) * 64;
        if (lane == 0) {
            sG[warp][0] = pt.x - kp.x;
            sG[warp][1] = pt.y - kp.y;
            sG[warp][2] = pt.z - kp.z;
        }
        sG[warp][3 + lane]  = vf[lane];
        sG[warp][35 + lane] = vf[32 + lane];
        __syncwarp();
        float a0 = 0.0f, a1 = 0.0f;
#pragma unroll
        for (int j = 0; j < 67; ++j) {
            float gj = sG[warp][j];
            a0 = fmaf(gj, sW0[j * 64 + lane], a0);
            a1 = fmaf(gj, sW0[j * 64 + 32 + lane], a1);
        }
        a0 = fmaxf(fmaf(a0, sS0[lane], sB0[lane]), 0.0f);
        a1 = fmaxf(fmaf(a1, sS0[32 + lane], sB0[32 + lane]), 0.0f);
        sH[warp][lane] = a0;
        sH[warp][32 + lane] = a1;
        __syncwarp();
        float c0 = 0.0f, c1 = 0.0f;
#pragma unroll
        for (int j = 0; j < 64; ++j) {
            float hj = sH[warp][j];
            c0 = fmaf(hj, sW1[j * 64 + lane], c0);
            c1 = fmaf(hj, sW1[j * 64 + 32 + lane], c1);
        }
        c0 = fmaxf(fmaf(c0, sS1[lane], sB1[lane]), 0.0f);
        c1 = fmaxf(fmaf(c1, sS1[32 + lane], sB1[32 + lane]), 0.0f);
        p0 = fmaxf(p0, c0);
        p1 = fmaxf(p1, c1);
        __syncwarp();
    }
    float* dst = g_feats + (size_t)gi * FDIM + 288 + lvl * 64;
    dst[lane]      = (cnt > 0) ? p0 : 0.0f;
    dst[32 + lane] = (cnt > 0) ? p1 : 0.0f;
}

// ---------------- fusion GEMM (4096x416 @ 416x128) + BN + ReLU ----------------
__global__ void fusion_kernel(const float* __restrict__ W, const float* __restrict__ gg,
                              const float* __restrict__ bb, float* __restrict__ out) {
    int warp = threadIdx.x >> 5, lane = threadIdx.x & 31;
    int row = blockIdx.x * 8 + warp;
    const float* a = g_feats + (size_t)row * FDIM;
    float acc0 = 0.f, acc1 = 0.f, acc2 = 0.f, acc3 = 0.f;
#pragma unroll 4
    for (int k = 0; k < FDIM; ++k) {
        float av = a[k];
        const float* wr = W + (size_t)k * 128;
        acc0 = fmaf(av, wr[lane], acc0);
        acc1 = fmaf(av, wr[32 + lane], acc1);
        acc2 = fmaf(av, wr[64 + lane], acc2);
        acc3 = fmaf(av, wr[96 + lane], acc3);
    }
    float* o = out + (size_t)row * 128;
    int c0 = lane, c1 = 32 + lane, c2 = 64 + lane, c3 = 96 + lane;
    o[c0] = fmaxf(fmaf(acc0, gg[c0] * BN_SCALE_F, bb[c0]), 0.0f);
    o[c1] = fmaxf(fmaf(acc1, gg[c1] * BN_SCALE_F, bb[c1]), 0.0f);
    o[c2] = fmaxf(fmaf(acc2, gg[c2] * BN_SCALE_F, bb[c2]), 0.0f);
    o[c3] = fmaxf(fmaf(acc3, gg[c3] * BN_SCALE_F, bb[c3]), 0.0f);
}

// ---------------- launch ----------------
extern "C" void kernel_launch(void* const* d_in, const int* in_sizes, int n_in,
                              void* d_out, int out_size) {
    const float* points  = (const float*)d_in[0];
    const float* spatial = (const float*)d_in[1];
    const int*   vcoords = (const int*)d_in[2];
    const float* vfeat   = (const float*)d_in[3];
    const float* raw_w0  = (const float*)d_in[4];
    const float* raw_g0  = (const float*)d_in[5];
    const float* raw_b0  = (const float*)d_in[6];
    const float* raw_w1  = (const float*)d_in[7];
    const float* raw_g1  = (const float*)d_in[8];
    const float* raw_b1  = (const float*)d_in[9];
    const float* conv_w0 = (const float*)d_in[10];
    const float* conv_g0 = (const float*)d_in[11];
    const float* conv_b0 = (const float*)d_in[12];
    const float* conv_w1 = (const float*)d_in[13];
    const float* conv_g1 = (const float*)d_in[14];
    const float* conv_b1 = (const float*)d_in[15];
    const float* fus_w   = (const float*)d_in[16];
    const float* fus_g   = (const float*)d_in[17];
    const float* fus_b   = (const float*)d_in[18];
    float* out = (float*)d_out;

    pack_raw_kernel<<<(BB * NRAW + 255) / 256, 256>>>(points);
    pack_conv_kernel<<<(BB * MVOX + 255) / 256, 256>>>(vcoords);
    fps_cluster_kernel<<<BB * FPS_G, FPS_THREADS>>>(points);
    bilinear_kernel<<<BB * NKP, 128>>>(spatial);
    scan_warp_kernel<false><<<dim3(NKP / 8, BB), 256>>>();
    scan_warp_kernel<true><<<dim3(NKP / 8, BB), 256>>>();
    raw_mlp_kernel<<<dim3(NKP / 128, 2, BB), 128>>>(raw_w0, raw_g0, raw_b0,
                                                    raw_w1, raw_g1, raw_b1);
    conv_mlp_kernel<<<dim3(NKP / 8, 2, BB), 256>>>(vfeat, conv_w0, conv_g0, conv_b0,
                                                   conv_w1, conv_g1, conv_b1);
    fusion_kernel<<<(BB * NKP) / 8, 256>>>(fus_w, fus_g, fus_b, out);
}

// round 4
// speedup vs baseline: 2.3426x; 2.3426x over previous
#include <cuda_runtime.h>

#define BB 2
#define NRAW 16384
#define NKP 2048
#define MVOX 8192
#define HBEV 200
#define WBEV 176
#define CBEV 256
#define FDIM 416
#define BN_SCALE_F 0.9999950000374997f

typedef unsigned short ushort_t;

// ---------------- scratch (static device globals; no allocation) ----------------
__device__ float4   g_kp[BB * NKP];          // keypoint xyz
__device__ float4   g_rawp[BB * NRAW];       // raw points: x,y,z,intensity
__device__ float4   g_convp[BB * MVOX];      // voxel centers
__device__ ushort_t g_ridx0[BB * NKP * 16];
__device__ ushort_t g_ridx1[BB * NKP * 16];
__device__ ushort_t g_cidx0[BB * NKP * 16];
__device__ ushort_t g_cidx1[BB * NKP * 32];
__device__ int      g_rcnt0[BB * NKP], g_rcnt1[BB * NKP];
__device__ int      g_ccnt0[BB * NKP], g_ccnt1[BB * NKP];
__device__ float    g_feats[BB * NKP * FDIM];

// ---------------- PTX helpers (cluster DSMEM + mbarrier) ----------------
__device__ __forceinline__ unsigned smem_u32(const void* p) {
    return (unsigned)__cvta_generic_to_shared(const_cast<void*>(p));
}
__device__ __forceinline__ unsigned cluster_rank() {
    unsigned r; asm("mov.u32 %0, %%cluster_ctarank;" : "=r"(r)); return r;
}
__device__ __forceinline__ unsigned mapa_u32(unsigned local, unsigned rank) {
    unsigned r;
    asm("mapa.shared::cluster.u32 %0, %1, %2;" : "=r"(r) : "r"(local), "r"(rank));
    return r;
}
__device__ __forceinline__ void st_cluster_f32(unsigned addr, float v) {
    asm volatile("st.shared::cluster.f32 [%0], %1;" :: "r"(addr), "f"(v) : "memory");
}
__device__ __forceinline__ void bar_init(unsigned addr, unsigned cnt) {
    asm volatile("mbarrier.init.shared.b64 [%0], %1;" :: "r"(addr), "r"(cnt) : "memory");
}
__device__ __forceinline__ void bar_arrive_cluster(unsigned addr) {
    asm volatile("mbarrier.arrive.release.cluster.shared::cluster.b64 _, [%0];"
                 :: "r"(addr) : "memory");
}
__device__ __forceinline__ void bar_wait_parity(unsigned addr, unsigned parity) {
    unsigned done;
    asm volatile("{\n\t.reg .pred p;\n\t"
                 "mbarrier.try_wait.parity.acquire.cluster.shared::cta.b64 p, [%1], %2, 0x989680;\n\t"
                 "selp.b32 %0, 1, 0, p;\n\t}"
                 : "=r"(done) : "r"(addr), "r"(parity) : "memory");
    while (!done) {
        asm volatile("{\n\t.reg .pred p;\n\t"
                     "mbarrier.try_wait.parity.acquire.cluster.shared::cta.b64 p, [%1], %2, 0x989680;\n\t"
                     "selp.b32 %0, 1, 0, p;\n\t}"
                     : "=r"(done) : "r"(addr), "r"(parity) : "memory");
    }
}
__device__ __forceinline__ void cluster_sync_all() {
    asm volatile("barrier.cluster.arrive.aligned;" ::: "memory");
    asm volatile("barrier.cluster.wait.aligned;" ::: "memory");
}

// ---------------- pack kernels ----------------
__global__ void pack_raw_kernel(const float* __restrict__ points) {
    int i = blockIdx.x * blockDim.x + threadIdx.x;
    if (i >= BB * NRAW) return;
    const float* r = points + (size_t)i * 5;
    g_rawp[i] = make_float4(r[1], r[2], r[3], r[4]);
}

__global__ void pack_conv_kernel(const int* __restrict__ vc) {
    int i = blockIdx.x * blockDim.x + threadIdx.x;
    if (i >= BB * MVOX) return;
    const int* r = vc + (size_t)i * 4;
    float cx = __fadd_rn(__fmul_rn(__fadd_rn((float)r[3], 0.5f), 0.2f), 0.0f);
    float cy = __fadd_rn(__fmul_rn(__fadd_rn((float)r[2], 0.5f), 0.2f), -40.0f);
    float cz = __fadd_rn(__fmul_rn(__fadd_rn((float)r[1], 0.5f), 0.4f), -3.0f);
    g_convp[i] = make_float4(cx, cy, cz, 0.0f);
}

// ---------------- FPS: 8-CTA cluster / batch, single-phase all-to-all exchange ----------------
#define FPS_G 8
#define FPS_THREADS 256
#define PTS_PER_CTA (NRAW / FPS_G)              // 2048
#define PTS_PER_THR (PTS_PER_CTA / FPS_THREADS) // 8

__global__ void __cluster_dims__(FPS_G, 1, 1)
__launch_bounds__(FPS_THREADS, 1)
fps_cluster_kernel(const float* __restrict__ points) {
    __shared__ float sx[PTS_PER_CTA], sy[PTS_PER_CTA], sz[PTS_PER_CTA];
    __shared__ float red_v[8]; __shared__ int red_i[8];
    // double-buffered exchange slots: [phase][field v,x,y,z][sender rank]
    __shared__ float sslot[2][4][8];
    __shared__ unsigned long long xbar[2];

    const int tid = threadIdx.x;
    const unsigned rank = cluster_rank();
    const int b = blockIdx.x / FPS_G;
    const int ctaBase = (int)rank * PTS_PER_CTA;
    const float* P = points + (size_t)b * NRAW * 5;
    const unsigned FULL = 0xffffffffu;

    if (tid == 0) {
        bar_init(smem_u32(&xbar[0]), FPS_G);
        bar_init(smem_u32(&xbar[1]), FPS_G);
    }
    __syncthreads();
    cluster_sync_all();   // barriers visible cluster-wide before any remote arrive

    // this CTA's 2048 points: registers (compute) + SMEM (winner coord lookup)
    float px[PTS_PER_THR], py[PTS_PER_THR], pz[PTS_PER_THR], dist[PTS_PER_THR];
#pragma unroll
    for (int j = 0; j < PTS_PER_THR; ++j) {
        int li = tid + j * FPS_THREADS;
        int gidx = ctaBase + li;
        float x = P[(size_t)gidx * 5 + 1];
        float y = P[(size_t)gidx * 5 + 2];
        float z = P[(size_t)gidx * 5 + 3];
        px[j] = x; py[j] = y; pz[j] = z;
        sx[li] = x; sy[li] = y; sz[li] = z;
        dist[j] = 1e10f;
    }
    __syncthreads();

    // initial winner = global point 0
    float wx = P[1], wy = P[2], wz = P[3];
    if (rank == 0 && tid == 0) g_kp[b * NKP] = make_float4(wx, wy, wz, 0.0f);

    // thread t (< 8) sends this CTA's winner to cluster CTA t
    unsigned rem_slot = 0, rem_bar = 0;
    if (tid < FPS_G) {
        rem_slot = mapa_u32(smem_u32(&sslot[0][0][rank]), (unsigned)tid);
        rem_bar  = mapa_u32(smem_u32(&xbar[0]), (unsigned)tid);
    }
    const unsigned loc_bar = smem_u32(&xbar[0]);
    unsigned par0 = 0, par1 = 0;

    for (int it = 1; it < NKP; ++it) {
        const int p = it & 1;
        // --- distance update + per-thread argmax (exact mul/add arithmetic) ---
        float bv = -1.0f; int bi = 0;
#pragma unroll
        for (int j = 0; j < PTS_PER_THR; ++j) {
            float dx = __fsub_rn(px[j], wx);
            float dy = __fsub_rn(py[j], wy);
            float dz = __fsub_rn(pz[j], wz);
            float d  = __fadd_rn(__fadd_rn(__fmul_rn(dx, dx), __fmul_rn(dy, dy)),
                                 __fmul_rn(dz, dz));
            float dm = fminf(dist[j], d);
            dist[j] = dm;
            if (dm > bv) { bv = dm; bi = tid + j * FPS_THREADS; }  // CTA-local index
        }
        // --- warp reduce (ties -> lowest local index) ---
#pragma unroll
        for (int off = 16; off > 0; off >>= 1) {
            float ov = __shfl_down_sync(FULL, bv, off);
            int   oi = __shfl_down_sync(FULL, bi, off);
            if (ov > bv || (ov == bv && oi < bi)) { bv = ov; bi = oi; }
        }
        if ((tid & 31) == 0) { red_v[tid >> 5] = bv; red_i[tid >> 5] = bi; }
        __syncthreads();

        // --- threads 0..7: redundant CTA reduce, then parallel all-to-all send ---
        if (tid < FPS_G) {
            float cv = red_v[0]; int ci = red_i[0];
#pragma unroll
            for (int w = 1; w < 8; ++w) {
                float v = red_v[w]; int i2 = red_i[w];
                if (v > cv || (v == cv && i2 < ci)) { cv = v; ci = i2; }
            }
            float cx = sx[ci], cy2 = sy[ci], cz2 = sz[ci];
            unsigned base = rem_slot + (unsigned)(p * 128);   // phase stride: 4 fields * 32B
            st_cluster_f32(base +  0, cv);
            st_cluster_f32(base + 32, cx);
            st_cluster_f32(base + 64, cy2);
            st_cluster_f32(base + 96, cz2);
            bar_arrive_cluster(rem_bar + (unsigned)(p * 8));
        }

        // --- all threads: wait for the 8 arrivals, reduce slots locally ---
        unsigned par = p ? par1 : par0;
        bar_wait_parity(loc_bar + (unsigned)(p * 8), par);
        if (p) par1 ^= 1; else par0 ^= 1;

        // ascending-rank scan with strict '>' == lowest-global-index tie-break
        float gv = sslot[p][0][0]; int rr = 0;
#pragma unroll
        for (int r = 1; r < FPS_G; ++r) {
            float v = sslot[p][0][r];
            if (v > gv) { gv = v; rr = r; }
        }
        wx = sslot[p][1][rr]; wy = sslot[p][2][rr]; wz = sslot[p][3][rr];
        if (rank == 0 && tid == 0) g_kp[b * NKP + it] = make_float4(wx, wy, wz, 0.0f);
    }
}

// ---------------- bilinear BEV sampling ----------------
__global__ void bilinear_kernel(const float* __restrict__ spatial) {
    int gi = blockIdx.x;              // b*NKP + m
    int b = gi / NKP;
    float4 kp = g_kp[gi];
    float xi = __fdiv_rn(__fdiv_rn(__fsub_rn(kp.x, 0.0f), 0.05f), 8.0f);
    float yi = __fdiv_rn(__fdiv_rn(__fsub_rn(kp.y, -40.0f), 0.05f), 8.0f);
    float xf = floorf(xi), yf = floorf(yi);
    int x0 = min(max((int)xf, 0), WBEV - 1);
    int x1 = min(max((int)xf + 1, 0), WBEV - 1);
    int y0 = min(max((int)yf, 0), HBEV - 1);
    int y1 = min(max((int)yf + 1, 0), HBEV - 1);
    float x0f = (float)x0, x1f = (float)x1, y0f = (float)y0, y1f = (float)y1;
    float wa = __fmul_rn(__fsub_rn(xi, x0f), __fsub_rn(y1f, yi));
    float wb = __fmul_rn(__fsub_rn(x1f, xi), __fsub_rn(y1f, yi));
    float wc = __fmul_rn(__fsub_rn(x1f, xi), __fsub_rn(yi, y0f));
    float wd = __fmul_rn(__fsub_rn(xi, x0f), __fsub_rn(yi, y0f));

    const float* sf = spatial + (size_t)b * CBEV * HBEV * WBEV;
    int o00 = y0 * WBEV + x0, o01 = y0 * WBEV + x1;
    int o10 = y1 * WBEV + x0, o11 = y1 * WBEV + x1;
    for (int c = threadIdx.x; c < CBEV; c += blockDim.x) {
        const float* ch = sf + (size_t)c * HBEV * WBEV;
        float fd = ch[o00], fc = ch[o01], fa = ch[o10], fb = ch[o11];
        float out = __fadd_rn(__fadd_rn(__fadd_rn(__fmul_rn(fd, wb), __fmul_rn(fc, wa)),
                                        __fmul_rn(fa, wc)), __fmul_rn(fb, wd));
        g_feats[(size_t)gi * FDIM + c] = out;
    }
}

// ---------------- ball-query: warp per keypoint, ballot first-N ascending ----------------
template <bool CONV>
__global__ void scan_warp_kernel() {
    constexpr int NPTS = CONV ? MVOX : NRAW;
    constexpr int NS0 = 16;
    constexpr int NS1 = CONV ? 32 : 16;
    const float R0SQ = CONV ? (float)(1.2 * 1.2) : (float)(0.4 * 0.4);
    const float R1SQ = CONV ? (float)(2.4 * 2.4) : (float)(0.8 * 0.8);
    const unsigned FULL = 0xffffffffu;

    int warp = threadIdx.x >> 5, lane = threadIdx.x & 31;
    int m = blockIdx.x * (blockDim.x >> 5) + warp;
    int b = blockIdx.y;
    int gi = b * NKP + m;
    float4 kp = g_kp[gi];
    const float4* pts = (CONV ? g_convp : g_rawp) + (size_t)b * NPTS;
    ushort_t* o0 = (CONV ? g_cidx0 : g_ridx0) + (size_t)gi * NS0;
    ushort_t* o1 = (CONV ? g_cidx1 : g_ridx1) + (size_t)gi * NS1;

    int c0 = 0, c1 = 0;
    const unsigned below = (1u << lane) - 1u;
    for (int base = 0; base < NPTS; base += 32) {
        float4 p = __ldg(&pts[base + lane]);
        float dx = __fsub_rn(kp.x, p.x);
        float dy = __fsub_rn(kp.y, p.y);
        float dz = __fsub_rn(kp.z, p.z);
        float d2 = __fadd_rn(__fadd_rn(__fmul_rn(dx, dx), __fmul_rn(dy, dy)),
                             __fmul_rn(dz, dz));
        bool h1 = d2 < R1SQ;
        bool h0 = d2 < R0SQ;
        unsigned m1 = __ballot_sync(FULL, h1);
        if (m1) {
            unsigned m0 = __ballot_sync(FULL, h0);
            if (h1) {
                int pos = c1 + __popc(m1 & below);
                if (pos < NS1) o1[pos] = (ushort_t)(base + lane);
            }
            if (h0) {
                int pos = c0 + __popc(m0 & below);
                if (pos < NS0) o0[pos] = (ushort_t)(base + lane);
            }
            c1 += __popc(m1);
            c0 += __popc(m0);
            if (c1 >= NS1 && c0 >= NS0) break;
        } else {
            __ballot_sync(FULL, h0);
        }
    }
    if (lane == 0) {
        if (CONV) { g_ccnt0[gi] = min(c0, NS0); g_ccnt1[gi] = min(c1, NS1); }
        else      { g_rcnt0[gi] = min(c0, NS0); g_rcnt1[gi] = min(c1, NS1); }
    }
}

// ---------------- raw SA MLP: thread per (kp, level), 4->16->16, maxpool ----------------
__global__ void raw_mlp_kernel(const float* __restrict__ w0, const float* __restrict__ gg0,
                               const float* __restrict__ bb0, const float* __restrict__ w1,
                               const float* __restrict__ gg1, const float* __restrict__ bb1) {
    int lvl = blockIdx.y, b = blockIdx.z;
    __shared__ float sW0[64], sW1[256], sS0[16], sB0[16], sS1[16], sB1[16];
    for (int i = threadIdx.x; i < 64; i += blockDim.x) sW0[i] = w0[lvl * 64 + i];
    for (int i = threadIdx.x; i < 256; i += blockDim.x) sW1[i] = w1[lvl * 256 + i];
    if (threadIdx.x < 16) {
        int c = threadIdx.x;
        sS0[c] = gg0[lvl * 16 + c] * BN_SCALE_F; sB0[c] = bb0[lvl * 16 + c];
        sS1[c] = gg1[lvl * 16 + c] * BN_SCALE_F; sB1[c] = bb1[lvl * 16 + c];
    }
    __syncthreads();

    int m = blockIdx.x * blockDim.x + threadIdx.x;
    int gi = b * NKP + m;
    int cnt = lvl ? g_rcnt1[gi] : g_rcnt0[gi];
    const ushort_t* idxarr = (lvl ? g_ridx1 : g_ridx0) + (size_t)gi * 16;
    float4 kp = g_kp[gi];

    float pooled[16];
#pragma unroll
    for (int c = 0; c < 16; ++c) pooled[c] = -1e30f;

    for (int s = 0; s < cnt; ++s) {
        int idx = idxarr[s];
        float4 p = g_rawp[(size_t)b * NRAW + idx];
        float g0v = p.x - kp.x, g1v = p.y - kp.y, g2v = p.z - kp.z, g3v = p.w;
        float h[16];
#pragma unroll
        for (int c = 0; c < 16; ++c) {
            float a = g0v * sW0[c] + g1v * sW0[16 + c] + g2v * sW0[32 + c] + g3v * sW0[48 + c];
            h[c] = fmaxf(fmaf(a, sS0[c], sB0[c]), 0.0f);
        }
#pragma unroll
        for (int c = 0; c < 16; ++c) {
            float a = 0.0f;
#pragma unroll
            for (int j = 0; j < 16; ++j) a = fmaf(h[j], sW1[j * 16 + c], a);
            float v = fmaxf(fmaf(a, sS1[c], sB1[c]), 0.0f);
            pooled[c] = fmaxf(pooled[c], v);
        }
    }
    float* dst = g_feats + (size_t)gi * FDIM + 256 + lvl * 16;
#pragma unroll
    for (int c = 0; c < 16; ++c) dst[c] = (cnt > 0) ? pooled[c] : 0.0f;
}

// ---------------- conv SA MLP: warp per (kp, level), 67->64->64, maxpool ----------------
__global__ void conv_mlp_kernel(const float* __restrict__ vfeat,
                                const float* __restrict__ w0, const float* __restrict__ gg0,
                                const float* __restrict__ bb0, const float* __restrict__ w1,
                                const float* __restrict__ gg1, const float* __restrict__ bb1) {
    int lvl = blockIdx.y, b = blockIdx.z;
    __shared__ float sW0[67 * 64], sW1[64 * 64];
    __shared__ float sS0[64], sB0[64], sS1[64], sB1[64];
    __shared__ float sG[8][68], sH[8][64];
    for (int i = threadIdx.x; i < 67 * 64; i += blockDim.x) sW0[i] = w0[lvl * 67 * 64 + i];
    for (int i = threadIdx.x; i < 64 * 64; i += blockDim.x) sW1[i] = w1[lvl * 64 * 64 + i];
    if (threadIdx.x < 64) {
        int c = threadIdx.x;
        sS0[c] = gg0[lvl * 64 + c] * BN_SCALE_F; sB0[c] = bb0[lvl * 64 + c];
        sS1[c] = gg1[lvl * 64 + c] * BN_SCALE_F; sB1[c] = bb1[lvl * 64 + c];
    }
    __syncthreads();

    int warp = threadIdx.x >> 5, lane = threadIdx.x & 31;
    int m = blockIdx.x * 8 + warp;
    int gi = b * NKP + m;
    int cnt = lvl ? g_ccnt1[gi] : g_ccnt0[gi];
    const ushort_t* idxarr = lvl ? (g_cidx1 + (size_t)gi * 32) : (g_cidx0 + (size_t)gi * 16);
    float4 kp = g_kp[gi];
    float p0 = -1e30f, p1 = -1e30f;

    for (int s = 0; s < cnt; ++s) {
        int idx = idxarr[s];
        float4 pt = g_convp[(size_t)b * MVOX + idx];
        const float* vf = vfeat + ((size_t)b * MVOX + idx) * 64;
        if (lane == 0) {
            sG[warp][0] = pt.x - kp.x;
            sG[warp][1] = pt.y - kp.y;
            sG[warp][2] = pt.z - kp.z;
        }
        sG[warp][3 + lane]  = vf[lane];
        sG[warp][35 + lane] = vf[32 + lane];
        __syncwarp();
        float a0 = 0.0f, a1 = 0.0f;
#pragma unroll
        for (int j = 0; j < 67; ++j) {
            float gj = sG[warp][j];
            a0 = fmaf(gj, sW0[j * 64 + lane], a0);
            a1 = fmaf(gj, sW0[j * 64 + 32 + lane], a1);
        }
        a0 = fmaxf(fmaf(a0, sS0[lane], sB0[lane]), 0.0f);
        a1 = fmaxf(fmaf(a1, sS0[32 + lane], sB0[32 + lane]), 0.0f);
        sH[warp][lane] = a0;
        sH[warp][32 + lane] = a1;
        __syncwarp();
        float c0 = 0.0f, c1 = 0.0f;
#pragma unroll
        for (int j = 0; j < 64; ++j) {
            float hj = sH[warp][j];
            c0 = fmaf(hj, sW1[j * 64 + lane], c0);
            c1 = fmaf(hj, sW1[j * 64 + 32 + lane], c1);
        }
        c0 = fmaxf(fmaf(c0, sS1[lane], sB1[lane]), 0.0f);
        c1 = fmaxf(fmaf(c1, sS1[32 + lane], sB1[32 + lane]), 0.0f);
        p0 = fmaxf(p0, c0);
        p1 = fmaxf(p1, c1);
        __syncwarp();
    }
    float* dst = g_feats + (size_t)gi * FDIM + 288 + lvl * 64;
    dst[lane]      = (cnt > 0) ? p0 : 0.0f;
    dst[32 + lane] = (cnt > 0) ? p1 : 0.0f;
}

// ---------------- fusion GEMM (4096x416 @ 416x128) + BN + ReLU ----------------
__global__ void fusion_kernel(const float* __restrict__ W, const float* __restrict__ gg,
                              const float* __restrict__ bb, float* __restrict__ out) {
    int warp = threadIdx.x >> 5, lane = threadIdx.x & 31;
    int row = blockIdx.x * 8 + warp;
    const float* a = g_feats + (size_t)row * FDIM;
    float acc0 = 0.f, acc1 = 0.f, acc2 = 0.f, acc3 = 0.f;
#pragma unroll 4
    for (int k = 0; k < FDIM; ++k) {
        float av = a[k];
        const float* wr = W + (size_t)k * 128;
        acc0 = fmaf(av, wr[lane], acc0);
        acc1 = fmaf(av, wr[32 + lane], acc1);
        acc2 = fmaf(av, wr[64 + lane], acc2);
        acc3 = fmaf(av, wr[96 + lane], acc3);
    }
    float* o = out + (size_t)row * 128;
    int c0 = lane, c1 = 32 + lane, c2 = 64 + lane, c3 = 96 + lane;
    o[c0] = fmaxf(fmaf(acc0, gg[c0] * BN_SCALE_F, bb[c0]), 0.0f);
    o[c1] = fmaxf(fmaf(acc1, gg[c1] * BN_SCALE_F, bb[c1]), 0.0f);
    o[c2] = fmaxf(fmaf(acc2, gg[c2] * BN_SCALE_F, bb[c2]), 0.0f);
    o[c3] = fmaxf(fmaf(acc3, gg[c3] * BN_SCALE_F, bb[c3]), 0.0f);
}

// ---------------- launch ----------------
extern "C" void kernel_launch(void* const* d_in, const int* in_sizes, int n_in,
                              void* d_out, int out_size) {
    const float* points  = (const float*)d_in[0];
    const float* spatial = (const float*)d_in[1];
    const int*   vcoords = (const int*)d_in[2];
    const float* vfeat   = (const float*)d_in[3];
    const float* raw_w0  = (const float*)d_in[4];
    const float* raw_g0  = (const float*)d_in[5];
    const float* raw_b0  = (const float*)d_in[6];
    const float* raw_w1  = (const float*)d_in[7];
    const float* raw_g1  = (const float*)d_in[8];
    const float* raw_b1  = (const float*)d_in[9];
    const float* conv_w0 = (const float*)d_in[10];
    const float* conv_g0 = (const float*)d_in[11];
    const float* conv_b0 = (const float*)d_in[12];
    const float* conv_w1 = (const float*)d_in[13];
    const float* conv_g1 = (const float*)d_in[14];
    const float* conv_b1 = (const float*)d_in[15];
    const float* fus_w   = (const float*)d_in[16];
    const float* fus_g   = (const float*)d_in[17];
    const float* fus_b   = (const float*)d_in[18];
    float* out = (float*)d_out;

    pack_raw_kernel<<<(BB * NRAW + 255) / 256, 256>>>(points);
    pack_conv_kernel<<<(BB * MVOX + 255) / 256, 256>>>(vcoords);
    fps_cluster_kernel<<<BB * FPS_G, FPS_THREADS>>>(points);
    bilinear_kernel<<<BB * NKP, 128>>>(spatial);
    scan_warp_kernel<false><<<dim3(NKP / 8, BB), 256>>>();
    scan_warp_kernel<true><<<dim3(NKP / 8, BB), 256>>>();
    raw_mlp_kernel<<<dim3(NKP / 128, 2, BB), 128>>>(raw_w0, raw_g0, raw_b0,
                                                    raw_w1, raw_g1, raw_b1);
    conv_mlp_kernel<<<dim3(NKP / 8, 2, BB), 256>>>(vfeat, conv_w0, conv_g0, conv_b0,
                                                   conv_w1, conv_g1, conv_b1);
    fusion_kernel<<<(BB * NKP) / 8, 256>>>(fus_w, fus_g, fus_b, out);
}

// round 5
// speedup vs baseline: 2.4698x; 1.0543x over previous
#include <cuda_runtime.h>

#define BB 2
#define NRAW 16384
#define NKP 2048
#define MVOX 8192
#define HBEV 200
#define WBEV 176
#define CBEV 256
#define FDIM 416
#define BN_SCALE_F 0.9999950000374997f

typedef unsigned short ushort_t;
typedef unsigned long long u64;

// ---------------- scratch (static device globals; no allocation) ----------------
__device__ float4   g_kp[BB * NKP];          // keypoint xyz
__device__ float4   g_rawp[BB * NRAW];       // raw points: x,y,z,intensity
__device__ float4   g_convp[BB * MVOX];      // voxel centers
__device__ ushort_t g_ridx0[BB * NKP * 16];
__device__ ushort_t g_ridx1[BB * NKP * 16];
__device__ ushort_t g_cidx0[BB * NKP * 16];
__device__ ushort_t g_cidx1[BB * NKP * 32];
__device__ int      g_rcnt0[BB * NKP], g_rcnt1[BB * NKP];
__device__ int      g_ccnt0[BB * NKP], g_ccnt1[BB * NKP];
__device__ float    g_feats[BB * NKP * FDIM];

// ---------------- PTX helpers (cluster DSMEM + mbarrier) ----------------
__device__ __forceinline__ unsigned smem_u32(const void* p) {
    return (unsigned)__cvta_generic_to_shared(const_cast<void*>(p));
}
__device__ __forceinline__ unsigned cluster_rank() {
    unsigned r; asm("mov.u32 %0, %%cluster_ctarank;" : "=r"(r)); return r;
}
__device__ __forceinline__ unsigned mapa_u32(unsigned local, unsigned rank) {
    unsigned r;
    asm("mapa.shared::cluster.u32 %0, %1, %2;" : "=r"(r) : "r"(local), "r"(rank));
    return r;
}
__device__ __forceinline__ void st_cluster_v4(unsigned addr, float a, float b,
                                              float c, float d) {
    asm volatile("st.shared::cluster.v4.f32 [%0], {%1, %2, %3, %4};"
                 :: "r"(addr), "f"(a), "f"(b), "f"(c), "f"(d) : "memory");
}
__device__ __forceinline__ void bar_init(unsigned addr, unsigned cnt) {
    asm volatile("mbarrier.init.shared.b64 [%0], %1;" :: "r"(addr), "r"(cnt) : "memory");
}
__device__ __forceinline__ void bar_arrive_cluster(unsigned addr) {
    asm volatile("mbarrier.arrive.release.cluster.shared::cluster.b64 _, [%0];"
                 :: "r"(addr) : "memory");
}
__device__ __forceinline__ void bar_wait_parity(unsigned addr, unsigned parity) {
    unsigned done;
    asm volatile("{\n\t.reg .pred p;\n\t"
                 "mbarrier.try_wait.parity.acquire.cluster.shared::cta.b64 p, [%1], %2, 0x989680;\n\t"
                 "selp.b32 %0, 1, 0, p;\n\t}"
                 : "=r"(done) : "r"(addr), "r"(parity) : "memory");
    while (!done) {
        asm volatile("{\n\t.reg .pred p;\n\t"
                     "mbarrier.try_wait.parity.acquire.cluster.shared::cta.b64 p, [%1], %2, 0x989680;\n\t"
                     "selp.b32 %0, 1, 0, p;\n\t}"
                     : "=r"(done) : "r"(addr), "r"(parity) : "memory");
    }
}
__device__ __forceinline__ void cluster_sync_all() {
    asm volatile("barrier.cluster.arrive.aligned;" ::: "memory");
    asm volatile("barrier.cluster.wait.aligned;" ::: "memory");
}

// ---------------- pack kernels ----------------
__global__ void pack_raw_kernel(const float* __restrict__ points) {
    int i = blockIdx.x * blockDim.x + threadIdx.x;
    if (i >= BB * NRAW) return;
    const float* r = points + (size_t)i * 5;
    g_rawp[i] = make_float4(r[1], r[2], r[3], r[4]);
}

__global__ void pack_conv_kernel(const int* __restrict__ vc) {
    int i = blockIdx.x * blockDim.x + threadIdx.x;
    if (i >= BB * MVOX) return;
    const int* r = vc + (size_t)i * 4;
    float cx = __fadd_rn(__fmul_rn(__fadd_rn((float)r[3], 0.5f), 0.2f), 0.0f);
    float cy = __fadd_rn(__fmul_rn(__fadd_rn((float)r[2], 0.5f), 0.2f), -40.0f);
    float cz = __fadd_rn(__fmul_rn(__fadd_rn((float)r[1], 0.5f), 0.4f), -3.0f);
    g_convp[i] = make_float4(cx, cy, cz, 0.0f);
}

// ---------------- FPS: 8-CTA cluster / batch, v4 all-to-all + packed u64 argmax ----------------
#define FPS_G 8
#define FPS_THREADS 256
#define PTS_PER_CTA (NRAW / FPS_G)              // 2048
#define PTS_PER_THR (PTS_PER_CTA / FPS_THREADS) // 8

__global__ void __cluster_dims__(FPS_G, 1, 1)
__launch_bounds__(FPS_THREADS, 1)
fps_cluster_kernel(const float* __restrict__ points) {
    __shared__ float sx[PTS_PER_CTA], sy[PTS_PER_CTA], sz[PTS_PER_CTA];
    __shared__ u64 red_k[8];
    // double-buffered exchange slots: [phase][sender rank] = {v, x, y, z}
    __shared__ float4 sslot[2][FPS_G];
    __shared__ unsigned long long xbar[2];

    const int tid = threadIdx.x;
    const unsigned rank = cluster_rank();
    const int b = blockIdx.x / FPS_G;
    const int ctaBase = (int)rank * PTS_PER_CTA;
    const float* P = points + (size_t)b * NRAW * 5;
    const unsigned FULL = 0xffffffffu;

    if (tid == 0) {
        bar_init(smem_u32(&xbar[0]), FPS_G);
        bar_init(smem_u32(&xbar[1]), FPS_G);
    }
    __syncthreads();
    cluster_sync_all();   // barriers visible cluster-wide before any remote arrive

    // this CTA's 2048 points: registers (compute) + SMEM (winner coord lookup)
    float px[PTS_PER_THR], py[PTS_PER_THR], pz[PTS_PER_THR], dist[PTS_PER_THR];
#pragma unroll
    for (int j = 0; j < PTS_PER_THR; ++j) {
        int li = tid + j * FPS_THREADS;
        int gidx = ctaBase + li;
        float x = P[(size_t)gidx * 5 + 1];
        float y = P[(size_t)gidx * 5 + 2];
        float z = P[(size_t)gidx * 5 + 3];
        px[j] = x; py[j] = y; pz[j] = z;
        sx[li] = x; sy[li] = y; sz[li] = z;
        dist[j] = 1e10f;
    }
    __syncthreads();

    // initial winner = global point 0
    float wx = P[1], wy = P[2], wz = P[3];
    if (rank == 0 && tid == 0) g_kp[b * NKP] = make_float4(wx, wy, wz, 0.0f);

    // thread t (< 8) sends this CTA's winner to cluster CTA t
    unsigned rem_slot = 0, rem_bar = 0;
    if (tid < FPS_G) {
        rem_slot = mapa_u32(smem_u32(&sslot[0][rank]), (unsigned)tid);
        rem_bar  = mapa_u32(smem_u32(&xbar[0]), (unsigned)tid);
    }
    const unsigned loc_bar = smem_u32(&xbar[0]);
    unsigned par0 = 0, par1 = 0;

    for (int it = 1; it < NKP; ++it) {
        const int p = it & 1;
        // --- distance update + per-thread argmax (exact mul/add arithmetic) ---
        float bv = -1.0f; int bi = 0;
#pragma unroll
        for (int j = 0; j < PTS_PER_THR; ++j) {
            float dx = __fsub_rn(px[j], wx);
            float dy = __fsub_rn(py[j], wy);
            float dz = __fsub_rn(pz[j], wz);
            float d  = __fadd_rn(__fadd_rn(__fmul_rn(dx, dx), __fmul_rn(dy, dy)),
                                 __fmul_rn(dz, dz));
            float dm = fminf(dist[j], d);
            dist[j] = dm;
            if (dm > bv) { bv = dm; bi = tid + j * FPS_THREADS; }  // CTA-local index
        }
        // --- pack into u64 key: (float bits << 32) | ~idx.  bv >= 0 here, so
        // unsigned-bit order == float order; u64 max == (v >, tie -> lowest idx) ---
        u64 key = ((u64)__float_as_uint(bv) << 32) | (unsigned)(~bi);
#pragma unroll
        for (int off = 16; off > 0; off >>= 1) {
            u64 ok = __shfl_down_sync(FULL, key, off);
            key = (ok > key) ? ok : key;
        }
        if ((tid & 31) == 0) red_k[tid >> 5] = key;
        __syncthreads();

        // --- threads 0..7: redundant CTA reduce, then parallel all-to-all send ---
        if (tid < FPS_G) {
            u64 ck = red_k[0];
#pragma unroll
            for (int w = 1; w < 8; ++w) {
                u64 v = red_k[w];
                ck = (v > ck) ? v : ck;
            }
            int ci = (int)(~(unsigned)ck);
            float cv = __uint_as_float((unsigned)(ck >> 32));
            st_cluster_v4(rem_slot + (unsigned)(p * (int)sizeof(float4) * FPS_G),
                          cv, sx[ci], sy[ci], sz[ci]);
            bar_arrive_cluster(rem_bar + (unsigned)(p * 8));
        }

        // --- all threads: wait for the 8 arrivals, reduce slots locally ---
        unsigned par = p ? par1 : par0;
        bar_wait_parity(loc_bar + (unsigned)(p * 8), par);
        if (p) par1 ^= 1; else par0 ^= 1;

        // ascending-rank scan with strict '>' == lowest-global-index tie-break
        float gv = sslot[p][0].x; int rr = 0;
#pragma unroll
        for (int r = 1; r < FPS_G; ++r) {
            float v = sslot[p][r].x;
            if (v > gv) { gv = v; rr = r; }
        }
        float4 win = sslot[p][rr];
        wx = win.y; wy = win.z; wz = win.w;
        if (rank == 0 && tid == 0) g_kp[b * NKP + it] = make_float4(wx, wy, wz, 0.0f);
    }
}

// ---------------- bilinear BEV sampling ----------------
__global__ void bilinear_kernel(const float* __restrict__ spatial) {
    int gi = blockIdx.x;              // b*NKP + m
    int b = gi / NKP;
    float4 kp = g_kp[gi];
    float xi = __fdiv_rn(__fdiv_rn(__fsub_rn(kp.x, 0.0f), 0.05f), 8.0f);
    float yi = __fdiv_rn(__fdiv_rn(__fsub_rn(kp.y, -40.0f), 0.05f), 8.0f);
    float xf = floorf(xi), yf = floorf(yi);
    int x0 = min(max((int)xf, 0), WBEV - 1);
    int x1 = min(max((int)xf + 1, 0), WBEV - 1);
    int y0 = min(max((int)yf, 0), HBEV - 1);
    int y1 = min(max((int)yf + 1, 0), HBEV - 1);
    float x0f = (float)x0, x1f = (float)x1, y0f = (float)y0, y1f = (float)y1;
    float wa = __fmul_rn(__fsub_rn(xi, x0f), __fsub_rn(y1f, yi));
    float wb = __fmul_rn(__fsub_rn(x1f, xi), __fsub_rn(y1f, yi));
    float wc = __fmul_rn(__fsub_rn(x1f, xi), __fsub_rn(yi, y0f));
    float wd = __fmul_rn(__fsub_rn(xi, x0f), __fsub_rn(yi, y0f));

    const float* sf = spatial + (size_t)b * CBEV * HBEV * WBEV;
    int o00 = y0 * WBEV + x0, o01 = y0 * WBEV + x1;
    int o10 = y1 * WBEV + x0, o11 = y1 * WBEV + x1;
    for (int c = threadIdx.x; c < CBEV; c += blockDim.x) {
        const float* ch = sf + (size_t)c * HBEV * WBEV;
        float fd = ch[o00], fc = ch[o01], fa = ch[o10], fb = ch[o11];
        float out = __fadd_rn(__fadd_rn(__fadd_rn(__fmul_rn(fd, wb), __fmul_rn(fc, wa)),
                                        __fmul_rn(fa, wc)), __fmul_rn(fb, wd));
        g_feats[(size_t)gi * FDIM + c] = out;
    }
}

// ---------------- ball-query: warp per keypoint, ballot first-N ascending ----------------
template <bool CONV>
__global__ void scan_warp_kernel() {
    constexpr int NPTS = CONV ? MVOX : NRAW;
    constexpr int NS0 = 16;
    constexpr int NS1 = CONV ? 32 : 16;
    const float R0SQ = CONV ? (float)(1.2 * 1.2) : (float)(0.4 * 0.4);
    const float R1SQ = CONV ? (float)(2.4 * 2.4) : (float)(0.8 * 0.8);
    const unsigned FULL = 0xffffffffu;

    int warp = threadIdx.x >> 5, lane = threadIdx.x & 31;
    int m = blockIdx.x * (blockDim.x >> 5) + warp;
    int b = blockIdx.y;
    int gi = b * NKP + m;
    float4 kp = g_kp[gi];
    const float4* pts = (CONV ? g_convp : g_rawp) + (size_t)b * NPTS;
    ushort_t* o0 = (CONV ? g_cidx0 : g_ridx0) + (size_t)gi * NS0;
    ushort_t* o1 = (CONV ? g_cidx1 : g_ridx1) + (size_t)gi * NS1;

    int c0 = 0, c1 = 0;
    const unsigned below = (1u << lane) - 1u;
    for (int base = 0; base < NPTS; base += 32) {
        float4 p = __ldg(&pts[base + lane]);
        float dx = __fsub_rn(kp.x, p.x);
        float dy = __fsub_rn(kp.y, p.y);
        float dz = __fsub_rn(kp.z, p.z);
        float d2 = __fadd_rn(__fadd_rn(__fmul_rn(dx, dx), __fmul_rn(dy, dy)),
                             __fmul_rn(dz, dz));
        bool h1 = d2 < R1SQ;
        bool h0 = d2 < R0SQ;
        unsigned m1 = __ballot_sync(FULL, h1);
        if (m1) {
            unsigned m0 = __ballot_sync(FULL, h0);
            if (h1) {
                int pos = c1 + __popc(m1 & below);
                if (pos < NS1) o1[pos] = (ushort_t)(base + lane);
            }
            if (h0) {
                int pos = c0 + __popc(m0 & below);
                if (pos < NS0) o0[pos] = (ushort_t)(base + lane);
            }
            c1 += __popc(m1);
            c0 += __popc(m0);
            if (c1 >= NS1 && c0 >= NS0) break;
        } else {
            __ballot_sync(FULL, h0);
        }
    }
    if (lane == 0) {
        if (CONV) { g_ccnt0[gi] = min(c0, NS0); g_ccnt1[gi] = min(c1, NS1); }
        else      { g_rcnt0[gi] = min(c0, NS0); g_rcnt1[gi] = min(c1, NS1); }
    }
}

// ---------------- raw SA MLP: thread per (kp, level), 4->16->16, maxpool ----------------
__global__ void raw_mlp_kernel(const float* __restrict__ w0, const float* __restrict__ gg0,
                               const float* __restrict__ bb0, const float* __restrict__ w1,
                               const float* __restrict__ gg1, const float* __restrict__ bb1) {
    int lvl = blockIdx.y, b = blockIdx.z;
    __shared__ float sW0[64], sW1[256], sS0[16], sB0[16], sS1[16], sB1[16];
    for (int i = threadIdx.x; i < 64; i += blockDim.x) sW0[i] = w0[lvl * 64 + i];
    for (int i = threadIdx.x; i < 256; i += blockDim.x) sW1[i] = w1[lvl * 256 + i];
    if (threadIdx.x < 16) {
        int c = threadIdx.x;
        sS0[c] = gg0[lvl * 16 + c] * BN_SCALE_F; sB0[c] = bb0[lvl * 16 + c];
        sS1[c] = gg1[lvl * 16 + c] * BN_SCALE_F; sB1[c] = bb1[lvl * 16 + c];
    }
    __syncthreads();

    int m = blockIdx.x * blockDim.x + threadIdx.x;
    int gi = b * NKP + m;
    int cnt = lvl ? g_rcnt1[gi] : g_rcnt0[gi];
    const ushort_t* idxarr = (lvl ? g_ridx1 : g_ridx0) + (size_t)gi * 16;
    float4 kp = g_kp[gi];

    float pooled[16];
#pragma unroll
    for (int c = 0; c < 16; ++c) pooled[c] = -1e30f;

    for (int s = 0; s < cnt; ++s) {
        int idx = idxarr[s];
        float4 p = g_rawp[(size_t)b * NRAW + idx];
        float g0v = p.x - kp.x, g1v = p.y - kp.y, g2v = p.z - kp.z, g3v = p.w;
        float h[16];
#pragma unroll
        for (int c = 0; c < 16; ++c) {
            float a = g0v * sW0[c] + g1v * sW0[16 + c] + g2v * sW0[32 + c] + g3v * sW0[48 + c];
            h[c] = fmaxf(fmaf(a, sS0[c], sB0[c]), 0.0f);
        }
#pragma unroll
        for (int c = 0; c < 16; ++c) {
            float a = 0.0f;
#pragma unroll
            for (int j = 0; j < 16; ++j) a = fmaf(h[j], sW1[j * 16 + c], a);
            float v = fmaxf(fmaf(a, sS1[c], sB1[c]), 0.0f);
            pooled[c] = fmaxf(pooled[c], v);
        }
    }
    float* dst = g_feats + (size_t)gi * FDIM + 256 + lvl * 16;
#pragma unroll
    for (int c = 0; c < 16; ++c) dst[c] = (cnt > 0) ? pooled[c] : 0.0f;
}

// ---------------- conv SA MLP: warp per (kp, level), 67->64->64, maxpool ----------------
__global__ void conv_mlp_kernel(const float* __restrict__ vfeat,
                                const float* __restrict__ w0, const float* __restrict__ gg0,
                                const float* __restrict__ bb0, const float* __restrict__ w1,
                                const float* __restrict__ gg1, const float* __restrict__ bb1) {
    int lvl = blockIdx.y, b = blockIdx.z;
    __shared__ float sW0[67 * 64], sW1[64 * 64];
    __shared__ float sS0[64], sB0[64], sS1[64], sB1[64];
    __shared__ float sG[8][68], sH[8][64];
    for (int i = threadIdx.x; i < 67 * 64; i += blockDim.x) sW0[i] = w0[lvl * 67 * 64 + i];
    for (int i = threadIdx.x; i < 64 * 64; i += blockDim.x) sW1[i] = w1[lvl * 64 * 64 + i];
    if (threadIdx.x < 64) {
        int c = threadIdx.x;
        sS0[c] = gg0[lvl * 64 + c] * BN_SCALE_F; sB0[c] = bb0[lvl * 64 + c];
        sS1[c] = gg1[lvl * 64 + c] * BN_SCALE_F; sB1[c] = bb1[lvl * 64 + c];
    }
    __syncthreads();

    int warp = threadIdx.x >> 5, lane = threadIdx.x & 31;
    int m = blockIdx.x * 8 + warp;
    int gi = b * NKP + m;
    int cnt = lvl ? g_ccnt1[gi] : g_ccnt0[gi];
    const ushort_t* idxarr = lvl ? (g_cidx1 + (size_t)gi * 32) : (g_cidx0 + (size_t)gi * 16);
    float4 kp = g_kp[gi];
    float p0 = -1e30f, p1 = -1e30f;

    for (int s = 0; s < cnt; ++s) {
        int idx = idxarr[s];
        float4 pt = g_convp[(size_t)b * MVOX + idx];
        const float* vf = vfeat + ((size_t)b * MVOX + idx) * 64;
        if (lane == 0) {
            sG[warp][0] = pt.x - kp.x;
            sG[warp][1] = pt.y - kp.y;
            sG[warp][2] = pt.z - kp.z;
        }
        sG[warp][3 + lane]  = vf[lane];
        sG[warp][35 + lane] = vf[32 + lane];
        __syncwarp();
        float a0 = 0.0f, a1 = 0.0f;
#pragma unroll
        for (int j = 0; j < 67; ++j) {
            float gj = sG[warp][j];
            a0 = fmaf(gj, sW0[j * 64 + lane], a0);
            a1 = fmaf(gj, sW0[j * 64 + 32 + lane], a1);
        }
        a0 = fmaxf(fmaf(a0, sS0[lane], sB0[lane]), 0.0f);
        a1 = fmaxf(fmaf(a1, sS0[32 + lane], sB0[32 + lane]), 0.0f);
        sH[warp][lane] = a0;
        sH[warp][32 + lane] = a1;
        __syncwarp();
        float c0 = 0.0f, c1 = 0.0f;
#pragma unroll
        for (int j = 0; j < 64; ++j) {
            float hj = sH[warp][j];
            c0 = fmaf(hj, sW1[j * 64 + lane], c0);
            c1 = fmaf(hj, sW1[j * 64 + 32 + lane], c1);
        }
        c0 = fmaxf(fmaf(c0, sS1[lane], sB1[lane]), 0.0f);
        c1 = fmaxf(fmaf(c1, sS1[32 + lane], sB1[32 + lane]), 0.0f);
        p0 = fmaxf(p0, c0);
        p1 = fmaxf(p1, c1);
        __syncwarp();
    }
    float* dst = g_feats + (size_t)gi * FDIM + 288 + lvl * 64;
    dst[lane]      = (cnt > 0) ? p0 : 0.0f;
    dst[32 + lane] = (cnt > 0) ? p1 : 0.0f;
}

// ---------------- fusion GEMM (4096x416 @ 416x128) + BN + ReLU ----------------
__global__ void fusion_kernel(const float* __restrict__ W, const float* __restrict__ gg,
                              const float* __restrict__ bb, float* __restrict__ out) {
    int warp = threadIdx.x >> 5, lane = threadIdx.x & 31;
    int row = blockIdx.x * 8 + warp;
    const float* a = g_feats + (size_t)row * FDIM;
    float acc0 = 0.f, acc1 = 0.f, acc2 = 0.f, acc3 = 0.f;
#pragma unroll 4
    for (int k = 0; k < FDIM; ++k) {
        float av = a[k];
        const float* wr = W + (size_t)k * 128;
        acc0 = fmaf(av, wr[lane], acc0);
        acc1 = fmaf(av, wr[32 + lane], acc1);
        acc2 = fmaf(av, wr[64 + lane], acc2);
        acc3 = fmaf(av, wr[96 + lane], acc3);
    }
    float* o = out + (size_t)row * 128;
    int c0 = lane, c1 = 32 + lane, c2 = 64 + lane, c3 = 96 + lane;
    o[c0] = fmaxf(fmaf(acc0, gg[c0] * BN_SCALE_F, bb[c0]), 0.0f);
    o[c1] = fmaxf(fmaf(acc1, gg[c1] * BN_SCALE_F, bb[c1]), 0.0f);
    o[c2] = fmaxf(fmaf(acc2, gg[c2] * BN_SCALE_F, bb[c2]), 0.0f);
    o[c3] = fmaxf(fmaf(acc3, gg[c3] * BN_SCALE_F, bb[c3]), 0.0f);
}

// ---------------- launch ----------------
extern "C" void kernel_launch(void* const* d_in, const int* in_sizes, int n_in,
                              void* d_out, int out_size) {
    const float* points  = (const float*)d_in[0];
    const float* spatial = (const float*)d_in[1];
    const int*   vcoords = (const int*)d_in[2];
    const float* vfeat   = (const float*)d_in[3];
    const float* raw_w0  = (const float*)d_in[4];
    const float* raw_g0  = (const float*)d_in[5];
    const float* raw_b0  = (const float*)d_in[6];
    const float* raw_w1  = (const float*)d_in[7];
    const float* raw_g1  = (const float*)d_in[8];
    const float* raw_b1  = (const float*)d_in[9];
    const float* conv_w0 = (const float*)d_in[10];
    const float* conv_g0 = (const float*)d_in[11];
    const float* conv_b0 = (const float*)d_in[12];
    const float* conv_w1 = (const float*)d_in[13];
    const float* conv_g1 = (const float*)d_in[14];
    const float* conv_b1 = (const float*)d_in[15];
    const float* fus_w   = (const float*)d_in[16];
    const float* fus_g   = (const float*)d_in[17];
    const float* fus_b   = (const float*)d_in[18];
    float* out = (float*)d_out;

    fps_cluster_kernel<<<BB * FPS_G, FPS_THREADS>>>(points);
    pack_raw_kernel<<<(BB * NRAW + 255) / 256, 256>>>(points);
    pack_conv_kernel<<<(BB * MVOX + 255) / 256, 256>>>(vcoords);
    bilinear_kernel<<<BB * NKP, 128>>>(spatial);
    scan_warp_kernel<false><<<dim3(NKP / 8, BB), 256>>>();
    scan_warp_kernel<true><<<dim3(NKP / 8, BB), 256>>>();
    raw_mlp_kernel<<<dim3(NKP / 128, 2, BB), 128>>>(raw_w0, raw_g0, raw_b0,
                                                    raw_w1, raw_g1, raw_b1);
    conv_mlp_kernel<<<dim3(NKP / 8, 2, BB), 256>>>(vfeat, conv_w0, conv_g0, conv_b0,
                                                   conv_w1, conv_g1, conv_b1);
    fusion_kernel<<<(BB * NKP) / 8, 256>>>(fus_w, fus_g, fus_b, out);
}

// round 6
// speedup vs baseline: 3.6408x; 1.4741x over previous
#include <cuda_runtime.h>

#define BB 2
#define NRAW 16384
#define NKP 2048
#define MVOX 8192
#define HBEV 200
#define WBEV 176
#define CBEV 256
#define FDIM 416
#define BN_SCALE_F 0.9999950000374997f

typedef unsigned short ushort_t;
typedef unsigned long long u64;

// ---------------- scratch (static device globals; no allocation) ----------------
__device__ float4   g_kp[BB * NKP];          // keypoint xyz
__device__ float4   g_rawp[BB * NRAW];       // raw points: x,y,z,intensity
__device__ float4   g_convp[BB * MVOX];      // voxel centers
__device__ ushort_t g_ridx0[BB * NKP * 16];
__device__ ushort_t g_ridx1[BB * NKP * 16];
__device__ ushort_t g_cidx0[BB * NKP * 16];
__device__ ushort_t g_cidx1[BB * NKP * 32];
__device__ int      g_rcnt0[BB * NKP], g_rcnt1[BB * NKP];
__device__ int      g_ccnt0[BB * NKP], g_ccnt1[BB * NKP];
__device__ float    g_feats[BB * NKP * FDIM];

// ---------------- PTX helpers (cluster DSMEM) ----------------
__device__ __forceinline__ unsigned smem_u32(const void* p) {
    return (unsigned)__cvta_generic_to_shared(const_cast<void*>(p));
}
__device__ __forceinline__ unsigned cluster_rank() {
    unsigned r; asm("mov.u32 %0, %%cluster_ctarank;" : "=r"(r)); return r;
}
__device__ __forceinline__ unsigned mapa_u32(unsigned local, unsigned rank) {
    unsigned r;
    asm("mapa.shared::cluster.u32 %0, %1, %2;" : "=r"(r) : "r"(local), "r"(rank));
    return r;
}
__device__ __forceinline__ void st_relaxed_cluster_u64(unsigned addr, u64 v) {
    asm volatile("st.relaxed.cluster.shared::cluster.b64 [%0], %1;"
                 :: "r"(addr), "l"(v) : "memory");
}
__device__ __forceinline__ u64 ld_vol_shared_u64(unsigned addr) {
    u64 v;
    asm volatile("ld.volatile.shared.b64 %0, [%1];" : "=l"(v) : "r"(addr) : "memory");
    return v;
}
__device__ __forceinline__ void st_vol_shared_u64(unsigned addr, u64 v) {
    asm volatile("st.volatile.shared.b64 [%0], %1;" :: "r"(addr), "l"(v) : "memory");
}
__device__ __forceinline__ void cluster_sync_all() {
    asm volatile("barrier.cluster.arrive.aligned;" ::: "memory");
    asm volatile("barrier.cluster.wait.aligned;" ::: "memory");
}

// ---------------- pack kernels ----------------
__global__ void pack_raw_kernel(const float* __restrict__ points) {
    int i = blockIdx.x * blockDim.x + threadIdx.x;
    if (i >= BB * NRAW) return;
    const float* r = points + (size_t)i * 5;
    g_rawp[i] = make_float4(r[1], r[2], r[3], r[4]);
}

__global__ void pack_conv_kernel(const int* __restrict__ vc) {
    int i = blockIdx.x * blockDim.x + threadIdx.x;
    if (i >= BB * MVOX) return;
    const int* r = vc + (size_t)i * 4;
    float cx = __fadd_rn(__fmul_rn(__fadd_rn((float)r[3], 0.5f), 0.2f), 0.0f);
    float cy = __fadd_rn(__fmul_rn(__fadd_rn((float)r[2], 0.5f), 0.2f), -40.0f);
    float cz = __fadd_rn(__fmul_rn(__fadd_rn((float)r[1], 0.5f), 0.4f), -3.0f);
    g_convp[i] = make_float4(cx, cy, cz, 0.0f);
}

// ---------------- FPS: 8-CTA cluster / batch, flag-free u64-key exchange ----------------
#define FPS_G 8
#define FPS_THREADS 256
#define PTS_PER_CTA (NRAW / FPS_G)              // 2048
#define PTS_PER_THR (PTS_PER_CTA / FPS_THREADS) // 8
#define FPS_SMEM_DYN (3 * NRAW * 4)             // full xyz copy per CTA: 192KB

__global__ void __cluster_dims__(FPS_G, 1, 1)
__launch_bounds__(FPS_THREADS, 1)
fps_cluster_kernel(const float* __restrict__ points) {
    extern __shared__ float dsh[];
    float* sx = dsh;
    float* sy = dsh + NRAW;
    float* sz = dsh + 2 * NRAW;
    __shared__ u64 red_k[8];
    __shared__ u64 slots[2][FPS_G];   // double-buffered; 0 == empty (keys never 0)

    const int tid = threadIdx.x;
    const unsigned rank = cluster_rank();
    const int b = blockIdx.x / FPS_G;
    const int ctaBase = (int)rank * PTS_PER_CTA;
    const float* P = points + (size_t)b * NRAW * 5;
    const unsigned FULL = 0xffffffffu;

    // zero both slot buffers before any cross-CTA traffic
    if (tid < 2 * FPS_G) ((u64*)slots)[tid] = 0ull;

    // every CTA loads ALL 16384 xyz into its own SMEM (winner lookup is local)
    for (int i = tid; i < NRAW; i += FPS_THREADS) {
        sx[i] = P[(size_t)i * 5 + 1];
        sy[i] = P[(size_t)i * 5 + 2];
        sz[i] = P[(size_t)i * 5 + 3];
    }
    __syncthreads();
    cluster_sync_all();   // all CTAs zeroed + loaded before any sends

    // this CTA's 2048-point slice in registers
    float px[PTS_PER_THR], py[PTS_PER_THR], pz[PTS_PER_THR], dist[PTS_PER_THR];
#pragma unroll
    for (int j = 0; j < PTS_PER_THR; ++j) {
        int gidx = ctaBase + tid + j * FPS_THREADS;
        px[j] = sx[gidx]; py[j] = sy[gidx]; pz[j] = sz[gidx];
        dist[j] = 1e10f;
    }

    // initial winner = global point 0
    float wx = sx[0], wy = sy[0], wz = sz[0];
    if (rank == 0 && tid == 0) g_kp[b * NKP] = make_float4(wx, wy, wz, 0.0f);

    // thread t (< 8) sends this CTA's winner key to cluster CTA t's slot[.][rank]
    unsigned rem_slot = 0;
    if (tid < FPS_G) rem_slot = mapa_u32(smem_u32(&slots[0][rank]), (unsigned)tid);
    const unsigned loc_slots = smem_u32(&slots[0][0]);

    for (int it = 1; it < NKP; ++it) {
        const int p = it & 1;
        const unsigned pofs = (unsigned)(p * FPS_G * 8);
        // --- distance update + per-thread argmax (exact mul/add arithmetic) ---
        float bv = -1.0f; int bi = 0;
#pragma unroll
        for (int j = 0; j < PTS_PER_THR; ++j) {
            float dx = __fsub_rn(px[j], wx);
            float dy = __fsub_rn(py[j], wy);
            float dz = __fsub_rn(pz[j], wz);
            float d  = __fadd_rn(__fadd_rn(__fmul_rn(dx, dx), __fmul_rn(dy, dy)),
                                 __fmul_rn(dz, dz));
            float dm = fminf(dist[j], d);
            dist[j] = dm;
            if (dm > bv) { bv = dm; bi = ctaBase + tid + j * FPS_THREADS; }  // GLOBAL idx
        }
        // --- warp argmax via redux: value max, then min global idx among ties ---
        unsigned vb = __float_as_uint(bv);                 // bv >= 0: u32 order == float order
        unsigned vmax = __reduce_max_sync(FULL, vb);
        unsigned cand = (vb == vmax) ? (unsigned)bi : 0xFFFFFFFFu;
        unsigned imin = __reduce_min_sync(FULL, cand);
        if ((tid & 31) == 0)
            red_k[tid >> 5] = ((u64)vmax << 32) | (unsigned)(~imin);
        __syncthreads();

        // --- threads 0..7: CTA reduce, single 8B relaxed remote store ---
        if (tid < FPS_G) {
            u64 ck = red_k[0];
#pragma unroll
            for (int w = 1; w < 8; ++w) { u64 v = red_k[w]; ck = (v > ck) ? v : ck; }
            st_relaxed_cluster_u64(rem_slot + pofs, ck);
        }

        // --- all threads: spin until all 8 slots for this phase are filled ---
        u64 k0, k1, k2, k3, k4, k5, k6, k7;
        for (;;) {
            k0 = ld_vol_shared_u64(loc_slots + pofs +  0);
            k1 = ld_vol_shared_u64(loc_slots + pofs +  8);
            k2 = ld_vol_shared_u64(loc_slots + pofs + 16);
            k3 = ld_vol_shared_u64(loc_slots + pofs + 24);
            k4 = ld_vol_shared_u64(loc_slots + pofs + 32);
            k5 = ld_vol_shared_u64(loc_slots + pofs + 40);
            k6 = ld_vol_shared_u64(loc_slots + pofs + 48);
            k7 = ld_vol_shared_u64(loc_slots + pofs + 56);
            if (k0 && k1 && k2 && k3 && k4 && k5 && k6 && k7) break;
        }
        // --- u64 max == global argmax with lowest-index tie-break ---
        u64 wk = k0;
        wk = (k1 > wk) ? k1 : wk; wk = (k2 > wk) ? k2 : wk;
        wk = (k3 > wk) ? k3 : wk; wk = (k4 > wk) ? k4 : wk;
        wk = (k5 > wk) ? k5 : wk; wk = (k6 > wk) ? k6 : wk;
        wk = (k7 > wk) ? k7 : wk;
        int gidx = (int)(~(unsigned)wk);
        wx = sx[gidx]; wy = sy[gidx]; wz = sz[gidx];
        if (rank == 0 && tid == 0) g_kp[b * NKP + it] = make_float4(wx, wy, wz, 0.0f);

        __syncthreads();                      // everyone done reading slots[p]
        if (tid < FPS_G)                      // reset before our next send (program order)
            st_vol_shared_u64(loc_slots + pofs + (unsigned)tid * 8, 0ull);
    }
}

// ---------------- bilinear BEV sampling ----------------
__global__ void bilinear_kernel(const float* __restrict__ spatial) {
    int gi = blockIdx.x;              // b*NKP + m
    int b = gi / NKP;
    float4 kp = g_kp[gi];
    float xi = __fdiv_rn(__fdiv_rn(__fsub_rn(kp.x, 0.0f), 0.05f), 8.0f);
    float yi = __fdiv_rn(__fdiv_rn(__fsub_rn(kp.y, -40.0f), 0.05f), 8.0f);
    float xf = floorf(xi), yf = floorf(yi);
    int x0 = min(max((int)xf, 0), WBEV - 1);
    int x1 = min(max((int)xf + 1, 0), WBEV - 1);
    int y0 = min(max((int)yf, 0), HBEV - 1);
    int y1 = min(max((int)yf + 1, 0), HBEV - 1);
    float x0f = (float)x0, x1f = (float)x1, y0f = (float)y0, y1f = (float)y1;
    float wa = __fmul_rn(__fsub_rn(xi, x0f), __fsub_rn(y1f, yi));
    float wb = __fmul_rn(__fsub_rn(x1f, xi), __fsub_rn(y1f, yi));
    float wc = __fmul_rn(__fsub_rn(x1f, xi), __fsub_rn(yi, y0f));
    float wd = __fmul_rn(__fsub_rn(xi, x0f), __fsub_rn(yi, y0f));

    const float* sf = spatial + (size_t)b * CBEV * HBEV * WBEV;
    int o00 = y0 * WBEV + x0, o01 = y0 * WBEV + x1;
    int o10 = y1 * WBEV + x0, o11 = y1 * WBEV + x1;
    for (int c = threadIdx.x; c < CBEV; c += blockDim.x) {
        const float* ch = sf + (size_t)c * HBEV * WBEV;
        float fd = ch[o00], fc = ch[o01], fa = ch[o10], fb = ch[o11];
        float out = __fadd_rn(__fadd_rn(__fadd_rn(__fmul_rn(fd, wb), __fmul_rn(fc, wa)),
                                        __fmul_rn(fa, wc)), __fmul_rn(fb, wd));
        g_feats[(size_t)gi * FDIM + c] = out;
    }
}

// ---------------- ball-query: warp per keypoint, ballot first-N ascending ----------------
template <bool CONV>
__global__ void scan_warp_kernel() {
    constexpr int NPTS = CONV ? MVOX : NRAW;
    constexpr int NS0 = 16;
    constexpr int NS1 = CONV ? 32 : 16;
    const float R0SQ = CONV ? (float)(1.2 * 1.2) : (float)(0.4 * 0.4);
    const float R1SQ = CONV ? (float)(2.4 * 2.4) : (float)(0.8 * 0.8);
    const unsigned FULL = 0xffffffffu;

    int warp = threadIdx.x >> 5, lane = threadIdx.x & 31;
    int m = blockIdx.x * (blockDim.x >> 5) + warp;
    int b = blockIdx.y;
    int gi = b * NKP + m;
    float4 kp = g_kp[gi];
    const float4* pts = (CONV ? g_convp : g_rawp) + (size_t)b * NPTS;
    ushort_t* o0 = (CONV ? g_cidx0 : g_ridx0) + (size_t)gi * NS0;
    ushort_t* o1 = (CONV ? g_cidx1 : g_ridx1) + (size_t)gi * NS1;

    int c0 = 0, c1 = 0;
    const unsigned below = (1u << lane) - 1u;
    for (int base = 0; base < NPTS; base += 32) {
        float4 p = __ldg(&pts[base + lane]);
        float dx = __fsub_rn(kp.x, p.x);
        float dy = __fsub_rn(kp.y, p.y);
        float dz = __fsub_rn(kp.z, p.z);
        float d2 = __fadd_rn(__fadd_rn(__fmul_rn(dx, dx), __fmul_rn(dy, dy)),
                             __fmul_rn(dz, dz));
        bool h1 = d2 < R1SQ;
        bool h0 = d2 < R0SQ;
        unsigned m1 = __ballot_sync(FULL, h1);
        if (m1) {
            unsigned m0 = __ballot_sync(FULL, h0);
            if (h1) {
                int pos = c1 + __popc(m1 & below);
                if (pos < NS1) o1[pos] = (ushort_t)(base + lane);
            }
            if (h0) {
                int pos = c0 + __popc(m0 & below);
                if (pos < NS0) o0[pos] = (ushort_t)(base + lane);
            }
            c1 += __popc(m1);
            c0 += __popc(m0);
            if (c1 >= NS1 && c0 >= NS0) break;
        } else {
            __ballot_sync(FULL, h0);
        }
    }
    if (lane == 0) {
        if (CONV) { g_ccnt0[gi] = min(c0, NS0); g_ccnt1[gi] = min(c1, NS1); }
        else      { g_rcnt0[gi] = min(c0, NS0); g_rcnt1[gi] = min(c1, NS1); }
    }
}

// ---------------- raw SA MLP: thread per (kp, level), 4->16->16, maxpool ----------------
__global__ void raw_mlp_kernel(const float* __restrict__ w0, const float* __restrict__ gg0,
                               const float* __restrict__ bb0, const float* __restrict__ w1,
                               const float* __restrict__ gg1, const float* __restrict__ bb1) {
    int lvl = blockIdx.y, b = blockIdx.z;
    __shared__ float sW0[64], sW1[256], sS0[16], sB0[16], sS1[16], sB1[16];
    for (int i = threadIdx.x; i < 64; i += blockDim.x) sW0[i] = w0[lvl * 64 + i];
    for (int i = threadIdx.x; i < 256; i += blockDim.x) sW1[i] = w1[lvl * 256 + i];
    if (threadIdx.x < 16) {
        int c = threadIdx.x;
        sS0[c] = gg0[lvl * 16 + c] * BN_SCALE_F; sB0[c] = bb0[lvl * 16 + c];
        sS1[c] = gg1[lvl * 16 + c] * BN_SCALE_F; sB1[c] = bb1[lvl * 16 + c];
    }
    __syncthreads();

    int m = blockIdx.x * blockDim.x + threadIdx.x;
    int gi = b * NKP + m;
    int cnt = lvl ? g_rcnt1[gi] : g_rcnt0[gi];
    const ushort_t* idxarr = (lvl ? g_ridx1 : g_ridx0) + (size_t)gi * 16;
    float4 kp = g_kp[gi];

    float pooled[16];
#pragma unroll
    for (int c = 0; c < 16; ++c) pooled[c] = -1e30f;

    for (int s = 0; s < cnt; ++s) {
        int idx = idxarr[s];
        float4 p = g_rawp[(size_t)b * NRAW + idx];
        float g0v = p.x - kp.x, g1v = p.y - kp.y, g2v = p.z - kp.z, g3v = p.w;
        float h[16];
#pragma unroll
        for (int c = 0; c < 16; ++c) {
            float a = g0v * sW0[c] + g1v * sW0[16 + c] + g2v * sW0[32 + c] + g3v * sW0[48 + c];
            h[c] = fmaxf(fmaf(a, sS0[c], sB0[c]), 0.0f);
        }
#pragma unroll
        for (int c = 0; c < 16; ++c) {
            float a = 0.0f;
#pragma unroll
            for (int j = 0; j < 16; ++j) a = fmaf(h[j], sW1[j * 16 + c], a);
            float v = fmaxf(fmaf(a, sS1[c], sB1[c]), 0.0f);
            pooled[c] = fmaxf(pooled[c], v);
        }
    }
    float* dst = g_feats + (size_t)gi * FDIM + 256 + lvl * 16;
#pragma unroll
    for (int c = 0; c < 16; ++c) dst[c] = (cnt > 0) ? pooled[c] : 0.0f;
}

// ---------------- conv SA MLP: warp per (kp, level), 67->64->64, maxpool ----------------
__global__ void conv_mlp_kernel(const float* __restrict__ vfeat,
                                const float* __restrict__ w0, const float* __restrict__ gg0,
                                const float* __restrict__ bb0, const float* __restrict__ w1,
                                const float* __restrict__ gg1, const float* __restrict__ bb1) {
    int lvl = blockIdx.y, b = blockIdx.z;
    __shared__ float sW0[67 * 64], sW1[64 * 64];
    __shared__ float sS0[64], sB0[64], sS1[64], sB1[64];
    __shared__ float sG[8][68], sH[8][64];
    for (int i = threadIdx.x; i < 67 * 64; i += blockDim.x) sW0[i] = w0[lvl * 67 * 64 + i];
    for (int i = threadIdx.x; i < 64 * 64; i += blockDim.x) sW1[i] = w1[lvl * 64 * 64 + i];
    if (threadIdx.x < 64) {
        int c = threadIdx.x;
        sS0[c] = gg0[lvl * 64 + c] * BN_SCALE_F; sB0[c] = bb0[lvl * 64 + c];
        sS1[c] = gg1[lvl * 64 + c] * BN_SCALE_F; sB1[c] = bb1[lvl * 64 + c];
    }
    __syncthreads();

    int warp = threadIdx.x >> 5, lane = threadIdx.x & 31;
    int m = blockIdx.x * 8 + warp;
    int gi = b * NKP + m;
    int cnt = lvl ? g_ccnt1[gi] : g_ccnt0[gi];
    const ushort_t* idxarr = lvl ? (g_cidx1 + (size_t)gi * 32) : (g_cidx0 + (size_t)gi * 16);
    float4 kp = g_kp[gi];
    float p0 = -1e30f, p1 = -1e30f;

    for (int s = 0; s < cnt; ++s) {
        int idx = idxarr[s];
        float4 pt = g_convp[(size_t)b * MVOX + idx];
        const float* vf = vfeat + ((size_t)b * MVOX + idx) * 64;
        if (lane == 0) {
            sG[warp][0] = pt.x - kp.x;
            sG[warp][1] = pt.y - kp.y;
            sG[warp][2] = pt.z - kp.z;
        }
        sG[warp][3 + lane]  = vf[lane];
        sG[warp][35 + lane] = vf[32 + lane];
        __syncwarp();
        float a0 = 0.0f, a1 = 0.0f;
#pragma unroll
        for (int j = 0; j < 67; ++j) {
            float gj = sG[warp][j];
            a0 = fmaf(gj, sW0[j * 64 + lane], a0);
            a1 = fmaf(gj, sW0[j * 64 + 32 + lane], a1);
        }
        a0 = fmaxf(fmaf(a0, sS0[lane], sB0[lane]), 0.0f);
        a1 = fmaxf(fmaf(a1, sS0[32 + lane], sB0[32 + lane]), 0.0f);
        sH[warp][lane] = a0;
        sH[warp][32 + lane] = a1;
        __syncwarp();
        float c0 = 0.0f, c1 = 0.0f;
#pragma unroll
        for (int j = 0; j < 64; ++j) {
            float hj = sH[warp][j];
            c0 = fmaf(hj, sW1[j * 64 + lane], c0);
            c1 = fmaf(hj, sW1[j * 64 + 32 + lane], c1);
        }
        c0 = fmaxf(fmaf(c0, sS1[lane], sB1[lane]), 0.0f);
        c1 = fmaxf(fmaf(c1, sS1[32 + lane], sB1[32 + lane]), 0.0f);
        p0 = fmaxf(p0, c0);
        p1 = fmaxf(p1, c1);
        __syncwarp();
    }
    float* dst = g_feats + (size_t)gi * FDIM + 288 + lvl * 64;
    dst[lane]      = (cnt > 0) ? p0 : 0.0f;
    dst[32 + lane] = (cnt > 0) ? p1 : 0.0f;
}

// ---------------- fusion GEMM (4096x416 @ 416x128) + BN + ReLU ----------------
__global__ void fusion_kernel(const float* __restrict__ W, const float* __restrict__ gg,
                              const float* __restrict__ bb, float* __restrict__ out) {
    int warp = threadIdx.x >> 5, lane = threadIdx.x & 31;
    int row = blockIdx.x * 8 + warp;
    const float* a = g_feats + (size_t)row * FDIM;
    float acc0 = 0.f, acc1 = 0.f, acc2 = 0.f, acc3 = 0.f;
#pragma unroll 4
    for (int k = 0; k < FDIM; ++k) {
        float av = a[k];
        const float* wr = W + (size_t)k * 128;
        acc0 = fmaf(av, wr[lane], acc0);
        acc1 = fmaf(av, wr[32 + lane], acc1);
        acc2 = fmaf(av, wr[64 + lane], acc2);
        acc3 = fmaf(av, wr[96 + lane], acc3);
    }
    float* o = out + (size_t)row * 128;
    int c0 = lane, c1 = 32 + lane, c2 = 64 + lane, c3 = 96 + lane;
    o[c0] = fmaxf(fmaf(acc0, gg[c0] * BN_SCALE_F, bb[c0]), 0.0f);
    o[c1] = fmaxf(fmaf(acc1, gg[c1] * BN_SCALE_F, bb[c1]), 0.0f);
    o[c2] = fmaxf(fmaf(acc2, gg[c2] * BN_SCALE_F, bb[c2]), 0.0f);
    o[c3] = fmaxf(fmaf(acc3, gg[c3] * BN_SCALE_F, bb[c3]), 0.0f);
}

// ---------------- launch ----------------
extern "C" void kernel_launch(void* const* d_in, const int* in_sizes, int n_in,
                              void* d_out, int out_size) {
    const float* points  = (const float*)d_in[0];
    const float* spatial = (const float*)d_in[1];
    const int*   vcoords = (const int*)d_in[2];
    const float* vfeat   = (const float*)d_in[3];
    const float* raw_w0  = (const float*)d_in[4];
    const float* raw_g0  = (const float*)d_in[5];
    const float* raw_b0  = (const float*)d_in[6];
    const float* raw_w1  = (const float*)d_in[7];
    const float* raw_g1  = (const float*)d_in[8];
    const float* raw_b1  = (const float*)d_in[9];
    const float* conv_w0 = (const float*)d_in[10];
    const float* conv_g0 = (const float*)d_in[11];
    const float* conv_b0 = (const float*)d_in[12];
    const float* conv_w1 = (const float*)d_in[13];
    const float* conv_g1 = (const float*)d_in[14];
    const float* conv_b1 = (const float*)d_in[15];
    const float* fus_w   = (const float*)d_in[16];
    const float* fus_g   = (const float*)d_in[17];
    const float* fus_b   = (const float*)d_in[18];
    float* out = (float*)d_out;

    cudaFuncSetAttribute(fps_cluster_kernel,
                         cudaFuncAttributeMaxDynamicSharedMemorySize, FPS_SMEM_DYN);

    fps_cluster_kernel<<<BB * FPS_G, FPS_THREADS, FPS_SMEM_DYN>>>(points);
    pack_raw_kernel<<<(BB * NRAW + 255) / 256, 256>>>(points);
    pack_conv_kernel<<<(BB * MVOX + 255) / 256, 256>>>(vcoords);
    bilinear_kernel<<<BB * NKP, 128>>>(spatial);
    scan_warp_kernel<false><<<dim3(NKP / 8, BB), 256>>>();
    scan_warp_kernel<true><<<dim3(NKP / 8, BB), 256>>>();
    raw_mlp_kernel<<<dim3(NKP / 128, 2, BB), 128>>>(raw_w0, raw_g0, raw_b0,
                                                    raw_w1, raw_g1, raw_b1);
    conv_mlp_kernel<<<dim3(NKP / 8, 2, BB), 256>>>(vfeat, conv_w0, conv_g0, conv_b0,
                                                   conv_w1, conv_g1, conv_b1);
    fusion_kernel<<<(BB * NKP) / 8, 256>>>(fus_w, fus_g, fus_b, out);
}